// round 2
// baseline (speedup 1.0000x reference)
#include <cuda_runtime.h>
#include <cuda_bf16.h>
#include <math.h>

// Problem constants
#define BS      4
#define SEQ     1024
#define DIM     1024
#define N_HEADS 16
#define D_HEAD  64
#define MROWS   (BS * SEQ)      // 4096

// ---------------------------------------------------------------------------
// Scratch (static device globals; no runtime allocation allowed)
// ---------------------------------------------------------------------------
__device__ float g_q  [MROWS * DIM];
__device__ float g_k  [MROWS * DIM];
__device__ float g_v  [MROWS * DIM];
__device__ float g_ctx[MROWS * DIM];

// ---------------------------------------------------------------------------
// SGEMM: C = alpha * (A @ B + bias)      A: MxK row-major, B: KxN row-major
// 128x128 block, BK=8, 8x8 per thread, 256 threads
// ---------------------------------------------------------------------------
#define BM 128
#define BN 128
#define BK 8
#define TM 8
#define TN 8

__global__ __launch_bounds__(256) void sgemm_bias_kernel(
    const float* __restrict__ A, const float* __restrict__ B,
    const float* __restrict__ bias, float* __restrict__ C,
    int M, int N, int K, float alpha)
{
    __shared__ float As[BK][BM];
    __shared__ float Bs[BK][BN];

    const int tid = threadIdx.x;
    const int bx  = blockIdx.x;   // N tile
    const int by  = blockIdx.y;   // M tile

    // A tile load: 128x8 = 1024 floats / 256 thr = one float4 each
    const int a_row = tid >> 1;          // 0..127
    const int a_col = (tid & 1) * 4;     // 0 or 4
    // B tile load: 8x128 = 1024 floats
    const int b_row = tid >> 5;          // 0..7
    const int b_col = (tid & 31) * 4;    // 0..124

    const float* Ab = A + (size_t)by * BM * K;
    const float* Bb = B + (size_t)bx * BN;

    const int trow = (tid >> 4) * TM;    // 0..120
    const int tcol = (tid & 15) * TN;    // 0..120

    float acc[TM][TN];
    #pragma unroll
    for (int i = 0; i < TM; i++)
        #pragma unroll
        for (int j = 0; j < TN; j++)
            acc[i][j] = 0.f;

    for (int k0 = 0; k0 < K; k0 += BK) {
        float4 av = *(const float4*)(Ab + (size_t)a_row * K + k0 + a_col);
        As[a_col + 0][a_row] = av.x;
        As[a_col + 1][a_row] = av.y;
        As[a_col + 2][a_row] = av.z;
        As[a_col + 3][a_row] = av.w;
        *(float4*)(&Bs[b_row][b_col]) =
            *(const float4*)(Bb + (size_t)(k0 + b_row) * N + b_col);
        __syncthreads();

        #pragma unroll
        for (int kk = 0; kk < BK; kk++) {
            float a_frag[TM], b_frag[TN];
            #pragma unroll
            for (int i = 0; i < TM; i += 4) {
                float4 t = *(const float4*)(&As[kk][trow + i]);
                a_frag[i + 0] = t.x; a_frag[i + 1] = t.y;
                a_frag[i + 2] = t.z; a_frag[i + 3] = t.w;
            }
            #pragma unroll
            for (int j = 0; j < TN; j += 4) {
                float4 t = *(const float4*)(&Bs[kk][tcol + j]);
                b_frag[j + 0] = t.x; b_frag[j + 1] = t.y;
                b_frag[j + 2] = t.z; b_frag[j + 3] = t.w;
            }
            #pragma unroll
            for (int i = 0; i < TM; i++)
                #pragma unroll
                for (int j = 0; j < TN; j++)
                    acc[i][j] = fmaf(a_frag[i], b_frag[j], acc[i][j]);
        }
        __syncthreads();
    }

    // epilogue: alpha * (acc + bias)
    #pragma unroll
    for (int i = 0; i < TM; i++) {
        const int row = by * BM + trow + i;
        #pragma unroll
        for (int j = 0; j < TN; j += 4) {
            float4 bv = *(const float4*)(bias + bx * BN + tcol + j);
            float4 cv;
            cv.x = alpha * (acc[i][j + 0] + bv.x);
            cv.y = alpha * (acc[i][j + 1] + bv.y);
            cv.z = alpha * (acc[i][j + 2] + bv.z);
            cv.w = alpha * (acc[i][j + 3] + bv.w);
            *(float4*)(C + (size_t)row * N + bx * BN + tcol + j) = cv;
        }
    }
}

// ---------------------------------------------------------------------------
// Flash attention with fused gauss reweight.
// softmax(s)*g / sum(softmax(s)*g) == exp(s - m)*g / sum(exp(s - m)*g),
// so g folds into the online-softmax weights directly.
// One thread = one query row. 128 rows / block. K/V tiles of 32 keys in smem.
// Q,K,V layout: (b*SEQ + s, DIM) row-major; head h occupies cols [h*64, h*64+64)
// grid: (SEQ/128, N_HEADS, BS)
// ---------------------------------------------------------------------------
#define TILE_K 32

__global__ __launch_bounds__(128) void flash_attn_kernel(
    const int* __restrict__ mask, const float* __restrict__ gauss)
{
    __shared__ float Ks[TILE_K][D_HEAD];
    __shared__ float Vs[TILE_K][D_HEAD];
    __shared__ float Gs[TILE_K];

    const int tid = threadIdx.x;
    const int b   = blockIdx.z;
    const int h   = blockIdx.y;
    const int row = blockIdx.x * 128 + tid;   // query position in [0, SEQ)

    // load q row (64 floats) into registers
    float4 q4[D_HEAD / 4];
    {
        const float* qp = g_q + ((size_t)(b * SEQ + row)) * DIM + h * D_HEAD;
        #pragma unroll
        for (int i = 0; i < D_HEAD / 4; i++)
            q4[i] = *(const float4*)(qp + i * 4);
    }

    float m = -1e30f, l = 0.f;
    float o[D_HEAD];
    #pragma unroll
    for (int d = 0; d < D_HEAD; d++) o[d] = 0.f;

    for (int kt = 0; kt < SEQ; kt += TILE_K) {
        // cooperative tile load: 32*64 floats each for K and V, float4s
        {
            const float* kbase = g_k + ((size_t)(b * SEQ + kt)) * DIM + h * D_HEAD;
            const float* vbase = g_v + ((size_t)(b * SEQ + kt)) * DIM + h * D_HEAD;
            #pragma unroll
            for (int i = 0; i < 4; i++) {
                int off = (i * 128 + tid) * 4;     // flat float offset in tile
                int j = off >> 6;                   // key within tile
                int d = off & 63;
                *(float4*)(&Ks[j][d]) = *(const float4*)(kbase + (size_t)j * DIM + d);
                *(float4*)(&Vs[j][d]) = *(const float4*)(vbase + (size_t)j * DIM + d);
            }
            if (tid < TILE_K) {
                int kk = kt + tid;
                float g = gauss[b * SEQ + kk] + 1e-10f;
                // fold the mask into g: masked key -> weight forced to 0 and
                // score left intact (exp stays finite; contribution is 0)
                Gs[tid] = (mask[b * SEQ + kk] == 0) ? 0.f : g;
            }
        }
        __syncthreads();

        // pass 1: scores for all 32 keys
        float s[TILE_K];
        float tmax = -1e30f;
        #pragma unroll
        for (int j = 0; j < TILE_K; j++) {
            float acc = 0.f;
            #pragma unroll
            for (int i = 0; i < D_HEAD / 4; i++) {
                float4 kv = *(const float4*)(&Ks[j][i * 4]);
                acc = fmaf(q4[i].x, kv.x, acc);
                acc = fmaf(q4[i].y, kv.y, acc);
                acc = fmaf(q4[i].z, kv.z, acc);
                acc = fmaf(q4[i].w, kv.w, acc);
            }
            // keys with zero gauss-weight (masked) cannot raise the max;
            // since g==0 kills them anyway, only exclude them from max
            s[j] = acc;
            float eff = (Gs[j] == 0.f) ? -1e30f : acc;
            tmax = fmaxf(tmax, eff);
        }

        const float mnew  = fmaxf(m, tmax);
        const float scale = __expf(m - mnew);
        l *= scale;
        #pragma unroll
        for (int d = 0; d < D_HEAD; d++) o[d] *= scale;

        // pass 2: accumulate
        #pragma unroll
        for (int j = 0; j < TILE_K; j++) {
            float p = __expf(s[j] - mnew) * Gs[j];
            l += p;
            #pragma unroll
            for (int d = 0; d < D_HEAD; d += 4) {
                float4 vv = *(const float4*)(&Vs[j][d]);
                o[d + 0] = fmaf(p, vv.x, o[d + 0]);
                o[d + 1] = fmaf(p, vv.y, o[d + 1]);
                o[d + 2] = fmaf(p, vv.z, o[d + 2]);
                o[d + 3] = fmaf(p, vv.w, o[d + 3]);
            }
        }
        m = mnew;
        __syncthreads();
    }

    const float inv_l = 1.f / l;
    float* op = g_ctx + ((size_t)(b * SEQ + row)) * DIM + h * D_HEAD;
    #pragma unroll
    for (int d = 0; d < D_HEAD; d += 4) {
        float4 cv;
        cv.x = o[d + 0] * inv_l;
        cv.y = o[d + 1] * inv_l;
        cv.z = o[d + 2] * inv_l;
        cv.w = o[d + 3] * inv_l;
        *(float4*)(op + d) = cv;
    }
}

// ---------------------------------------------------------------------------
// Launch
// inputs: 0=query 1=key 2=value 3=mask 4=gauss_weight
//         5=Wq 6=bq 7=Wk 8=bk 9=Wv 10=bv 11=Wo 12=bo
// ---------------------------------------------------------------------------
extern "C" void kernel_launch(void* const* d_in, const int* in_sizes, int n_in,
                              void* d_out, int out_size)
{
    const float* query = (const float*)d_in[0];
    const float* key   = (const float*)d_in[1];
    const float* value = (const float*)d_in[2];
    const int*   mask  = (const int*)  d_in[3];
    const float* gauss = (const float*)d_in[4];
    const float* Wq = (const float*)d_in[5];
    const float* bq = (const float*)d_in[6];
    const float* Wk = (const float*)d_in[7];
    const float* bk = (const float*)d_in[8];
    const float* Wv = (const float*)d_in[9];
    const float* bv = (const float*)d_in[10];
    const float* Wo = (const float*)d_in[11];
    const float* bo = (const float*)d_in[12];
    float* out = (float*)d_out;

    float *pq, *pk, *pv, *pctx;
    cudaGetSymbolAddress((void**)&pq,   g_q);
    cudaGetSymbolAddress((void**)&pk,   g_k);
    cudaGetSymbolAddress((void**)&pv,   g_v);
    cudaGetSymbolAddress((void**)&pctx, g_ctx);

    dim3 ggrid(DIM / BN, MROWS / BM);   // (8, 32)
    const float qscale = 1.0f / 8.0f;   // 1/sqrt(D_HEAD)

    sgemm_bias_kernel<<<ggrid, 256>>>(query, Wq, bq, pq, MROWS, DIM, DIM, qscale);
    sgemm_bias_kernel<<<ggrid, 256>>>(key,   Wk, bk, pk, MROWS, DIM, DIM, 1.0f);
    sgemm_bias_kernel<<<ggrid, 256>>>(value, Wv, bv, pv, MROWS, DIM, DIM, 1.0f);

    dim3 agrid(SEQ / 128, N_HEADS, BS); // (8, 16, 4)
    flash_attn_kernel<<<agrid, 128>>>(mask, gauss);

    sgemm_bias_kernel<<<ggrid, 256>>>(pctx, Wo, bo, out, MROWS, DIM, DIM, 1.0f);
}

// round 3
// speedup vs baseline: 1.0013x; 1.0013x over previous
#include <cuda_runtime.h>
#include <cuda_bf16.h>
#include <math.h>

// Problem constants
#define BS      4
#define SEQ     1024
#define DIM     1024
#define N_HEADS 16
#define D_HEAD  64
#define MROWS   (BS * SEQ)      // 4096

// ---------------------------------------------------------------------------
// Scratch (static device globals; no runtime allocation allowed)
// ---------------------------------------------------------------------------
__device__ float g_q  [MROWS * DIM];
__device__ float g_k  [MROWS * DIM];
__device__ float g_v  [MROWS * DIM];
__device__ float g_ctx[MROWS * DIM];

// ---------------------------------------------------------------------------
// SGEMM: C = alpha * (A @ B + bias)      A: MxK row-major, B: KxN row-major
// 128x128 block, BK=8, 8x8 per thread, 256 threads
// ---------------------------------------------------------------------------
#define BM 128
#define BN 128
#define BK 8
#define TM 8
#define TN 8

__global__ __launch_bounds__(256) void sgemm_bias_kernel(
    const float* __restrict__ A, const float* __restrict__ B,
    const float* __restrict__ bias, float* __restrict__ C,
    int M, int N, int K, float alpha)
{
    __shared__ float As[BK][BM];
    __shared__ float Bs[BK][BN];

    const int tid = threadIdx.x;
    const int bx  = blockIdx.x;   // N tile
    const int by  = blockIdx.y;   // M tile

    // A tile load: 128x8 = 1024 floats / 256 thr = one float4 each
    const int a_row = tid >> 1;          // 0..127
    const int a_col = (tid & 1) * 4;     // 0 or 4
    // B tile load: 8x128 = 1024 floats
    const int b_row = tid >> 5;          // 0..7
    const int b_col = (tid & 31) * 4;    // 0..124

    const float* Ab = A + (size_t)by * BM * K;
    const float* Bb = B + (size_t)bx * BN;

    const int trow = (tid >> 4) * TM;    // 0..120
    const int tcol = (tid & 15) * TN;    // 0..120

    float acc[TM][TN];
    #pragma unroll
    for (int i = 0; i < TM; i++)
        #pragma unroll
        for (int j = 0; j < TN; j++)
            acc[i][j] = 0.f;

    for (int k0 = 0; k0 < K; k0 += BK) {
        float4 av = *(const float4*)(Ab + (size_t)a_row * K + k0 + a_col);
        As[a_col + 0][a_row] = av.x;
        As[a_col + 1][a_row] = av.y;
        As[a_col + 2][a_row] = av.z;
        As[a_col + 3][a_row] = av.w;
        *(float4*)(&Bs[b_row][b_col]) =
            *(const float4*)(Bb + (size_t)(k0 + b_row) * N + b_col);
        __syncthreads();

        #pragma unroll
        for (int kk = 0; kk < BK; kk++) {
            float a_frag[TM], b_frag[TN];
            #pragma unroll
            for (int i = 0; i < TM; i += 4) {
                float4 t = *(const float4*)(&As[kk][trow + i]);
                a_frag[i + 0] = t.x; a_frag[i + 1] = t.y;
                a_frag[i + 2] = t.z; a_frag[i + 3] = t.w;
            }
            #pragma unroll
            for (int j = 0; j < TN; j += 4) {
                float4 t = *(const float4*)(&Bs[kk][tcol + j]);
                b_frag[j + 0] = t.x; b_frag[j + 1] = t.y;
                b_frag[j + 2] = t.z; b_frag[j + 3] = t.w;
            }
            #pragma unroll
            for (int i = 0; i < TM; i++)
                #pragma unroll
                for (int j = 0; j < TN; j++)
                    acc[i][j] = fmaf(a_frag[i], b_frag[j], acc[i][j]);
        }
        __syncthreads();
    }

    // epilogue: alpha * (acc + bias)
    #pragma unroll
    for (int i = 0; i < TM; i++) {
        const int row = by * BM + trow + i;
        #pragma unroll
        for (int j = 0; j < TN; j += 4) {
            float4 bv = *(const float4*)(bias + bx * BN + tcol + j);
            float4 cv;
            cv.x = alpha * (acc[i][j + 0] + bv.x);
            cv.y = alpha * (acc[i][j + 1] + bv.y);
            cv.z = alpha * (acc[i][j + 2] + bv.z);
            cv.w = alpha * (acc[i][j + 3] + bv.w);
            *(float4*)(C + (size_t)row * N + bx * BN + tcol + j) = cv;
        }
    }
}

// ---------------------------------------------------------------------------
// Flash attention with fused gauss reweight.
// softmax(s)*g / sum(softmax(s)*g) == exp(s - m)*g / sum(exp(s - m)*g),
// so g folds into the online-softmax weights directly.
// One thread = one query row. 128 rows / block. K/V tiles of 32 keys in smem.
// Q,K,V layout: (b*SEQ + s, DIM) row-major; head h occupies cols [h*64, h*64+64)
// grid: (SEQ/128, N_HEADS, BS)
// ---------------------------------------------------------------------------
#define TILE_K 32

__global__ __launch_bounds__(128) void flash_attn_kernel(
    const int* __restrict__ mask, const float* __restrict__ gauss)
{
    __shared__ float Ks[TILE_K][D_HEAD];
    __shared__ float Vs[TILE_K][D_HEAD];
    __shared__ float Gs[TILE_K];

    const int tid = threadIdx.x;
    const int b   = blockIdx.z;
    const int h   = blockIdx.y;
    const int row = blockIdx.x * 128 + tid;   // query position in [0, SEQ)

    // load q row (64 floats) into registers
    float4 q4[D_HEAD / 4];
    {
        const float* qp = g_q + ((size_t)(b * SEQ + row)) * DIM + h * D_HEAD;
        #pragma unroll
        for (int i = 0; i < D_HEAD / 4; i++)
            q4[i] = *(const float4*)(qp + i * 4);
    }

    float m = -1e30f, l = 0.f;
    float o[D_HEAD];
    #pragma unroll
    for (int d = 0; d < D_HEAD; d++) o[d] = 0.f;

    for (int kt = 0; kt < SEQ; kt += TILE_K) {
        // cooperative tile load: 32*64 floats each for K and V, float4s
        {
            const float* kbase = g_k + ((size_t)(b * SEQ + kt)) * DIM + h * D_HEAD;
            const float* vbase = g_v + ((size_t)(b * SEQ + kt)) * DIM + h * D_HEAD;
            #pragma unroll
            for (int i = 0; i < 4; i++) {
                int off = (i * 128 + tid) * 4;     // flat float offset in tile
                int j = off >> 6;                   // key within tile
                int d = off & 63;
                *(float4*)(&Ks[j][d]) = *(const float4*)(kbase + (size_t)j * DIM + d);
                *(float4*)(&Vs[j][d]) = *(const float4*)(vbase + (size_t)j * DIM + d);
            }
            if (tid < TILE_K) {
                int kk = kt + tid;
                float g = gauss[b * SEQ + kk] + 1e-10f;
                // fold the mask into g: masked key -> weight forced to 0 and
                // score left intact (exp stays finite; contribution is 0)
                Gs[tid] = (mask[b * SEQ + kk] == 0) ? 0.f : g;
            }
        }
        __syncthreads();

        // pass 1: scores for all 32 keys
        float s[TILE_K];
        float tmax = -1e30f;
        #pragma unroll
        for (int j = 0; j < TILE_K; j++) {
            float acc = 0.f;
            #pragma unroll
            for (int i = 0; i < D_HEAD / 4; i++) {
                float4 kv = *(const float4*)(&Ks[j][i * 4]);
                acc = fmaf(q4[i].x, kv.x, acc);
                acc = fmaf(q4[i].y, kv.y, acc);
                acc = fmaf(q4[i].z, kv.z, acc);
                acc = fmaf(q4[i].w, kv.w, acc);
            }
            // keys with zero gauss-weight (masked) cannot raise the max;
            // since g==0 kills them anyway, only exclude them from max
            s[j] = acc;
            float eff = (Gs[j] == 0.f) ? -1e30f : acc;
            tmax = fmaxf(tmax, eff);
        }

        const float mnew  = fmaxf(m, tmax);
        const float scale = __expf(m - mnew);
        l *= scale;
        #pragma unroll
        for (int d = 0; d < D_HEAD; d++) o[d] *= scale;

        // pass 2: accumulate
        #pragma unroll
        for (int j = 0; j < TILE_K; j++) {
            float p = __expf(s[j] - mnew) * Gs[j];
            l += p;
            #pragma unroll
            for (int d = 0; d < D_HEAD; d += 4) {
                float4 vv = *(const float4*)(&Vs[j][d]);
                o[d + 0] = fmaf(p, vv.x, o[d + 0]);
                o[d + 1] = fmaf(p, vv.y, o[d + 1]);
                o[d + 2] = fmaf(p, vv.z, o[d + 2]);
                o[d + 3] = fmaf(p, vv.w, o[d + 3]);
            }
        }
        m = mnew;
        __syncthreads();
    }

    const float inv_l = 1.f / l;
    float* op = g_ctx + ((size_t)(b * SEQ + row)) * DIM + h * D_HEAD;
    #pragma unroll
    for (int d = 0; d < D_HEAD; d += 4) {
        float4 cv;
        cv.x = o[d + 0] * inv_l;
        cv.y = o[d + 1] * inv_l;
        cv.z = o[d + 2] * inv_l;
        cv.w = o[d + 3] * inv_l;
        *(float4*)(op + d) = cv;
    }
}

// ---------------------------------------------------------------------------
// Launch
// inputs: 0=query 1=key 2=value 3=mask 4=gauss_weight
//         5=Wq 6=bq 7=Wk 8=bk 9=Wv 10=bv 11=Wo 12=bo
// ---------------------------------------------------------------------------
extern "C" void kernel_launch(void* const* d_in, const int* in_sizes, int n_in,
                              void* d_out, int out_size)
{
    const float* query = (const float*)d_in[0];
    const float* key   = (const float*)d_in[1];
    const float* value = (const float*)d_in[2];
    const int*   mask  = (const int*)  d_in[3];
    const float* gauss = (const float*)d_in[4];
    const float* Wq = (const float*)d_in[5];
    const float* bq = (const float*)d_in[6];
    const float* Wk = (const float*)d_in[7];
    const float* bk = (const float*)d_in[8];
    const float* Wv = (const float*)d_in[9];
    const float* bv = (const float*)d_in[10];
    const float* Wo = (const float*)d_in[11];
    const float* bo = (const float*)d_in[12];
    float* out = (float*)d_out;

    float *pq, *pk, *pv, *pctx;
    cudaGetSymbolAddress((void**)&pq,   g_q);
    cudaGetSymbolAddress((void**)&pk,   g_k);
    cudaGetSymbolAddress((void**)&pv,   g_v);
    cudaGetSymbolAddress((void**)&pctx, g_ctx);

    dim3 ggrid(DIM / BN, MROWS / BM);   // (8, 32)
    const float qscale = 1.0f / 8.0f;   // 1/sqrt(D_HEAD)

    sgemm_bias_kernel<<<ggrid, 256>>>(query, Wq, bq, pq, MROWS, DIM, DIM, qscale);
    sgemm_bias_kernel<<<ggrid, 256>>>(key,   Wk, bk, pk, MROWS, DIM, DIM, 1.0f);
    sgemm_bias_kernel<<<ggrid, 256>>>(value, Wv, bv, pv, MROWS, DIM, DIM, 1.0f);

    dim3 agrid(SEQ / 128, N_HEADS, BS); // (8, 16, 4)
    flash_attn_kernel<<<agrid, 128>>>(mask, gauss);

    sgemm_bias_kernel<<<ggrid, 256>>>(pctx, Wo, bo, out, MROWS, DIM, DIM, 1.0f);
}

// round 4
// speedup vs baseline: 1.0778x; 1.0765x over previous
#include <cuda_runtime.h>
#include <cuda_bf16.h>
#include <math.h>

// Problem constants
#define BS      4
#define SEQ     1024
#define DIM     1024
#define N_HEADS 16
#define D_HEAD  64
#define MROWS   (BS * SEQ)      // 4096

// ---------------------------------------------------------------------------
// Scratch (static device globals; no runtime allocation allowed)
// ---------------------------------------------------------------------------
__device__ float g_q  [MROWS * DIM];
__device__ float g_k  [MROWS * DIM];
__device__ float g_v  [MROWS * DIM];
__device__ float g_ctx[MROWS * DIM];

// ---------------------------------------------------------------------------
// SGEMM: C = alpha * (A @ B + bias)    A: MxK row-major, B: KxN row-major
// 128x128 block, BK=16, double-buffered smem, 8x8 per thread, 256 threads
// ---------------------------------------------------------------------------
#define BM 128
#define BN 128
#define BKD 16
#define TM 8
#define TN 8

__global__ __launch_bounds__(256, 2) void sgemm_db_kernel(
    const float* __restrict__ A, const float* __restrict__ B,
    const float* __restrict__ bias, float* __restrict__ C,
    int K, float alpha)
{
    __shared__ float As[2][BKD][BM];
    __shared__ float Bs[2][BKD][BN];

    const int tid = threadIdx.x;
    const int bx  = blockIdx.x;   // N tile
    const int by  = blockIdx.y;   // M tile

    // A tile: 128 rows x 16 cols -> 2 float4 per thread
    const int a_row = tid >> 1;           // 0..127
    const int a_cb  = (tid & 1) * 8;      // 0 or 8
    // B tile: 16 rows x 128 cols -> 2 float4 per thread
    const int b_col = (tid & 31) * 4;     // 0..124
    const int b_r0  = tid >> 5;           // 0..7  (second row = +8)

    const float* Ab = A + (size_t)by * BM * K;
    const float* Bb = B + (size_t)bx * BN;

    const int trow = (tid >> 4) * TM;     // 0..120
    const int tcol = (tid & 15) * TN;     // 0..120

    float acc[TM][TN];
    #pragma unroll
    for (int i = 0; i < TM; i++)
        #pragma unroll
        for (int j = 0; j < TN; j++)
            acc[i][j] = 0.f;

    float4 av0, av1, bv0, bv1;

    // preload tile 0
    av0 = *(const float4*)(Ab + (size_t)a_row * K + a_cb);
    av1 = *(const float4*)(Ab + (size_t)a_row * K + a_cb + 4);
    bv0 = *(const float4*)(Bb + (size_t)b_r0 * DIM + b_col);
    bv1 = *(const float4*)(Bb + (size_t)(b_r0 + 8) * DIM + b_col);
    As[0][a_cb + 0][a_row] = av0.x; As[0][a_cb + 1][a_row] = av0.y;
    As[0][a_cb + 2][a_row] = av0.z; As[0][a_cb + 3][a_row] = av0.w;
    As[0][a_cb + 4][a_row] = av1.x; As[0][a_cb + 5][a_row] = av1.y;
    As[0][a_cb + 6][a_row] = av1.z; As[0][a_cb + 7][a_row] = av1.w;
    *(float4*)(&Bs[0][b_r0][b_col])     = bv0;
    *(float4*)(&Bs[0][b_r0 + 8][b_col]) = bv1;
    __syncthreads();

    int cur = 0;
    for (int k0 = 0; k0 < K; k0 += BKD) {
        const bool has_next = (k0 + BKD) < K;
        if (has_next) {
            const int kn = k0 + BKD;
            av0 = *(const float4*)(Ab + (size_t)a_row * K + kn + a_cb);
            av1 = *(const float4*)(Ab + (size_t)a_row * K + kn + a_cb + 4);
            bv0 = *(const float4*)(Bb + (size_t)(kn + b_r0) * DIM + b_col);
            bv1 = *(const float4*)(Bb + (size_t)(kn + b_r0 + 8) * DIM + b_col);
        }

        #pragma unroll
        for (int kk = 0; kk < BKD; kk++) {
            float a_frag[TM], b_frag[TN];
            #pragma unroll
            for (int i = 0; i < TM; i += 4) {
                float4 t = *(const float4*)(&As[cur][kk][trow + i]);
                a_frag[i + 0] = t.x; a_frag[i + 1] = t.y;
                a_frag[i + 2] = t.z; a_frag[i + 3] = t.w;
            }
            #pragma unroll
            for (int j = 0; j < TN; j += 4) {
                float4 t = *(const float4*)(&Bs[cur][kk][tcol + j]);
                b_frag[j + 0] = t.x; b_frag[j + 1] = t.y;
                b_frag[j + 2] = t.z; b_frag[j + 3] = t.w;
            }
            #pragma unroll
            for (int i = 0; i < TM; i++)
                #pragma unroll
                for (int j = 0; j < TN; j++)
                    acc[i][j] = fmaf(a_frag[i], b_frag[j], acc[i][j]);
        }

        if (has_next) {
            const int nxt = cur ^ 1;
            As[nxt][a_cb + 0][a_row] = av0.x; As[nxt][a_cb + 1][a_row] = av0.y;
            As[nxt][a_cb + 2][a_row] = av0.z; As[nxt][a_cb + 3][a_row] = av0.w;
            As[nxt][a_cb + 4][a_row] = av1.x; As[nxt][a_cb + 5][a_row] = av1.y;
            As[nxt][a_cb + 6][a_row] = av1.z; As[nxt][a_cb + 7][a_row] = av1.w;
            *(float4*)(&Bs[nxt][b_r0][b_col])     = bv0;
            *(float4*)(&Bs[nxt][b_r0 + 8][b_col]) = bv1;
            cur = nxt;
            __syncthreads();
        }
    }

    // epilogue: alpha * (acc + bias)
    #pragma unroll
    for (int i = 0; i < TM; i++) {
        const int row = by * BM + trow + i;
        #pragma unroll
        for (int j = 0; j < TN; j += 4) {
            float4 bv = *(const float4*)(bias + bx * BN + tcol + j);
            float4 cv;
            cv.x = alpha * (acc[i][j + 0] + bv.x);
            cv.y = alpha * (acc[i][j + 1] + bv.y);
            cv.z = alpha * (acc[i][j + 2] + bv.z);
            cv.w = alpha * (acc[i][j + 3] + bv.w);
            *(float4*)(C + (size_t)row * DIM + bx * BN + tcol + j) = cv;
        }
    }
}

// ---------------------------------------------------------------------------
// Flash attention v2 (block-cooperative, SGEMM-style register tiling).
// softmax(s)*g / sum(softmax(s)*g) == exp(s-m)*g / sum(exp(s-m)*g):
// gauss weight folds into online-softmax weights.
//
// Block: 128 queries x one head. 256 threads as (ty,tx)=(16,16).
// Each thread: 8 query rows (ty*8..) x 4 key cols / 4 output dims (tx*4..).
// Tiles of 64 keys. Q and K live transposed in smem (d-major) so both
// S=Q·Kt and O+=P·V phases use float4 fragment loads (10.7 FMA / LDS.128).
// P is staged through smem (written transposed, k-major).
// ---------------------------------------------------------------------------
#define BQ   128
#define BKT  64
#define KSTR 68     // padded k/v row stride (floats)
#define PSTR 132    // padded P row stride (floats)

#define QS_OFF 0                       // Qs[64][128]   (d-major)
#define KS_OFF 8192                    // Ks[64][68]    (d-major)
#define VS_OFF (KS_OFF + 64*KSTR)      // Vs[64][68]    (k-major, natural)
#define PS_OFF (VS_OFF + 64*KSTR)      // Ps[64][132]   (k-major)
#define GS_OFF (PS_OFF + 64*PSTR)      // Gs[64]
#define FSMEM_FLOATS (GS_OFF + 64)
#define FSMEM_BYTES  (FSMEM_FLOATS * 4)

__global__ __launch_bounds__(256, 2) void flash_attn2_kernel(
    const int* __restrict__ mask, const float* __restrict__ gauss)
{
    extern __shared__ float sm[];
    float* Qs = sm + QS_OFF;
    float* Ks = sm + KS_OFF;
    float* Vs = sm + VS_OFF;
    float* Ps = sm + PS_OFF;
    float* Gs = sm + GS_OFF;

    const int tid = threadIdx.x;
    const int tx  = tid & 15;
    const int ty  = tid >> 4;
    const int b   = blockIdx.z;
    const int h   = blockIdx.y;
    const int qbase = blockIdx.x * BQ;

    // ---- load Q block transposed into Qs[d][q] (once) ----
    {
        const float* qg = g_q + ((size_t)(b * SEQ + qbase)) * DIM + h * D_HEAD;
        #pragma unroll
        for (int c = 0; c < 8; c++) {
            int flat = (c * 256 + tid) * 4;       // 8192 floats total
            int qr = flat >> 6;                    // 0..127
            int d  = flat & 63;
            float4 v = *(const float4*)(qg + (size_t)qr * DIM + d);
            Qs[(d + 0) * 128 + qr] = v.x;
            Qs[(d + 1) * 128 + qr] = v.y;
            Qs[(d + 2) * 128 + qr] = v.z;
            Qs[(d + 3) * 128 + qr] = v.w;
        }
    }

    float m[8], l[8], O[8][4];
    #pragma unroll
    for (int i = 0; i < 8; i++) {
        m[i] = -1e30f; l[i] = 0.f;
        #pragma unroll
        for (int j = 0; j < 4; j++) O[i][j] = 0.f;
    }

    for (int kt = 0; kt < SEQ; kt += BKT) {
        // ---- load tile: K transposed (d-major), V natural (k-major) ----
        {
            const float* kg = g_k + ((size_t)(b * SEQ + kt)) * DIM + h * D_HEAD;
            const float* vg = g_v + ((size_t)(b * SEQ + kt)) * DIM + h * D_HEAD;
            #pragma unroll
            for (int c = 0; c < 4; c++) {
                int flat = (c * 256 + tid) * 4;    // 4096 floats total
                int kr = flat >> 6;                 // 0..63
                int d  = flat & 63;
                float4 kv = *(const float4*)(kg + (size_t)kr * DIM + d);
                Ks[(d + 0) * KSTR + kr] = kv.x;
                Ks[(d + 1) * KSTR + kr] = kv.y;
                Ks[(d + 2) * KSTR + kr] = kv.z;
                Ks[(d + 3) * KSTR + kr] = kv.w;
                *(float4*)(Vs + (size_t)kr * KSTR + d) =
                    *(const float4*)(vg + (size_t)kr * DIM + d);
            }
            if (tid < BKT) {
                int kk = kt + tid;
                float g = gauss[b * SEQ + kk] + 1e-10f;
                Gs[tid] = (mask[b * SEQ + kk] == 0) ? 0.f : g;
            }
        }
        __syncthreads();

        // ---- S = Q · Kt  (reduction over d) ----
        float S[8][4];
        #pragma unroll
        for (int i = 0; i < 8; i++)
            #pragma unroll
            for (int j = 0; j < 4; j++) S[i][j] = 0.f;

        #pragma unroll 8
        for (int kk = 0; kk < D_HEAD; kk++) {
            float4 a0 = *(const float4*)(Qs + kk * 128 + ty * 8);
            float4 a1 = *(const float4*)(Qs + kk * 128 + ty * 8 + 4);
            float4 bb = *(const float4*)(Ks + kk * KSTR + tx * 4);
            float a_frag[8] = {a0.x, a0.y, a0.z, a0.w, a1.x, a1.y, a1.z, a1.w};
            float b_frag[4] = {bb.x, bb.y, bb.z, bb.w};
            #pragma unroll
            for (int i = 0; i < 8; i++)
                #pragma unroll
                for (int j = 0; j < 4; j++)
                    S[i][j] = fmaf(a_frag[i], b_frag[j], S[i][j]);
        }

        // ---- online softmax with gauss fold ----
        float g4[4];
        #pragma unroll
        for (int j = 0; j < 4; j++) g4[j] = Gs[tx * 4 + j];

        #pragma unroll
        for (int i = 0; i < 8; i++) {
            float eff[4];
            float lm = -1e30f;
            #pragma unroll
            for (int j = 0; j < 4; j++) {
                eff[j] = (g4[j] > 0.f) ? S[i][j] : -1e30f;
                lm = fmaxf(lm, eff[j]);
            }
            // max over the 16 lanes sharing this row block
            #pragma unroll
            for (int off = 8; off >= 1; off >>= 1)
                lm = fmaxf(lm, __shfl_xor_sync(0xffffffffu, lm, off));

            float mnew  = fmaxf(m[i], lm);
            float scale = __expf(m[i] - mnew);
            float rs = 0.f;
            #pragma unroll
            for (int j = 0; j < 4; j++) {
                float p = g4[j] * __expf(eff[j] - mnew);
                S[i][j] = p;          // S now holds P
                rs += p;
            }
            #pragma unroll
            for (int off = 8; off >= 1; off >>= 1)
                rs += __shfl_xor_sync(0xffffffffu, rs, off);

            l[i] = l[i] * scale + rs;
            m[i] = mnew;
            #pragma unroll
            for (int j = 0; j < 4; j++) O[i][j] *= scale;
        }

        // ---- write P transposed: Ps[k][q] ----
        #pragma unroll
        for (int j = 0; j < 4; j++) {
            float4 v0 = make_float4(S[0][j], S[1][j], S[2][j], S[3][j]);
            float4 v1 = make_float4(S[4][j], S[5][j], S[6][j], S[7][j]);
            *(float4*)(Ps + (tx * 4 + j) * PSTR + ty * 8)     = v0;
            *(float4*)(Ps + (tx * 4 + j) * PSTR + ty * 8 + 4) = v1;
        }
        __syncthreads();

        // ---- O += P · V  (reduction over keys) ----
        #pragma unroll 8
        for (int kk = 0; kk < BKT; kk++) {
            float4 a0 = *(const float4*)(Ps + kk * PSTR + ty * 8);
            float4 a1 = *(const float4*)(Ps + kk * PSTR + ty * 8 + 4);
            float4 bb = *(const float4*)(Vs + kk * KSTR + tx * 4);
            float a_frag[8] = {a0.x, a0.y, a0.z, a0.w, a1.x, a1.y, a1.z, a1.w};
            float b_frag[4] = {bb.x, bb.y, bb.z, bb.w};
            #pragma unroll
            for (int i = 0; i < 8; i++)
                #pragma unroll
                for (int j = 0; j < 4; j++)
                    O[i][j] = fmaf(a_frag[i], b_frag[j], O[i][j]);
        }
        __syncthreads();
    }

    // ---- epilogue ----
    #pragma unroll
    for (int i = 0; i < 8; i++) {
        float inv = 1.f / l[i];
        float4 ov = make_float4(O[i][0] * inv, O[i][1] * inv,
                                O[i][2] * inv, O[i][3] * inv);
        int row = qbase + ty * 8 + i;
        *(float4*)(g_ctx + ((size_t)(b * SEQ + row)) * DIM + h * D_HEAD + tx * 4) = ov;
    }
}

// ---------------------------------------------------------------------------
// Launch
// inputs: 0=query 1=key 2=value 3=mask 4=gauss_weight
//         5=Wq 6=bq 7=Wk 8=bk 9=Wv 10=bv 11=Wo 12=bo
// ---------------------------------------------------------------------------
extern "C" void kernel_launch(void* const* d_in, const int* in_sizes, int n_in,
                              void* d_out, int out_size)
{
    const float* query = (const float*)d_in[0];
    const float* key   = (const float*)d_in[1];
    const float* value = (const float*)d_in[2];
    const int*   mask  = (const int*)  d_in[3];
    const float* gauss = (const float*)d_in[4];
    const float* Wq = (const float*)d_in[5];
    const float* bq = (const float*)d_in[6];
    const float* Wk = (const float*)d_in[7];
    const float* bk = (const float*)d_in[8];
    const float* Wv = (const float*)d_in[9];
    const float* bv = (const float*)d_in[10];
    const float* Wo = (const float*)d_in[11];
    const float* bo = (const float*)d_in[12];
    float* out = (float*)d_out;

    float *pq, *pk, *pv, *pctx;
    cudaGetSymbolAddress((void**)&pq,   g_q);
    cudaGetSymbolAddress((void**)&pk,   g_k);
    cudaGetSymbolAddress((void**)&pv,   g_v);
    cudaGetSymbolAddress((void**)&pctx, g_ctx);

    // allow >48KB dynamic smem for flash kernel (idempotent host call,
    // not a stream op -> safe under graph capture)
    cudaFuncSetAttribute(flash_attn2_kernel,
                         cudaFuncAttributeMaxDynamicSharedMemorySize,
                         FSMEM_BYTES);

    dim3 ggrid(DIM / BN, MROWS / BM);   // (8, 32)
    const float qscale = 1.0f / 8.0f;   // 1/sqrt(D_HEAD)

    sgemm_db_kernel<<<ggrid, 256>>>(query, Wq, bq, pq, DIM, qscale);
    sgemm_db_kernel<<<ggrid, 256>>>(key,   Wk, bk, pk, DIM, 1.0f);
    sgemm_db_kernel<<<ggrid, 256>>>(value, Wv, bv, pv, DIM, 1.0f);

    dim3 agrid(SEQ / BQ, N_HEADS, BS);  // (8, 16, 4)
    flash_attn2_kernel<<<agrid, 256, FSMEM_BYTES>>>(mask, gauss);

    sgemm_db_kernel<<<ggrid, 256>>>(pctx, Wo, bo, out, DIM, 1.0f);
}

// round 7
// speedup vs baseline: 1.6387x; 1.5204x over previous
#include <cuda_runtime.h>
#include <cuda_bf16.h>
#include <math.h>

// Problem constants
#define BS      4
#define SEQ     1024
#define DIM     1024
#define N_HEADS 16
#define D_HEAD  64
#define MROWS   (BS * SEQ)      // 4096

// ---------------------------------------------------------------------------
// Scratch (static device globals; no runtime allocation allowed)
// ---------------------------------------------------------------------------
__device__ float g_q  [MROWS * DIM];
__device__ float g_k  [MROWS * DIM];
__device__ float g_v  [MROWS * DIM];
__device__ float g_ctx[MROWS * DIM];

// ---------------------------------------------------------------------------
// TF32 tensor-core GEMM: C = alpha * (A @ B + bias)
// A: MxK row-major, B: KxN row-major (N = DIM), bias: N
// Block tile 128x128, BK=32, 256 threads = 8 warps, warp tile 64x32.
// mma.sync.aligned.m16n8k8.row.col.f32.tf32.tf32.f32
// Smem (DYNAMIC, 69632B > 48KB static cap): As[2][32][136], Bs[2][32][136]
//   (136 % 32 == 8  ->  conflict-free fragment loads & stores).
// ---------------------------------------------------------------------------
#define GBM 128
#define GBN 128
#define GBK 32
#define GSTR 136
#define GEMM_BUF_WORDS (GBK * GSTR)                 // 4352 per buffer
#define GEMM_SMEM_WORDS (4 * GEMM_BUF_WORDS)        // As[2] + Bs[2]
#define GEMM_SMEM_BYTES (GEMM_SMEM_WORDS * 4)       // 69632

__device__ __forceinline__ unsigned f2tf32(float f) {
    unsigned u;
    asm("cvt.rna.tf32.f32 %0, %1;" : "=r"(u) : "f"(f));
    return u;
}

__device__ __forceinline__ void mma_tf32(float c[4],
    unsigned a0, unsigned a1, unsigned a2, unsigned a3,
    unsigned b0, unsigned b1)
{
    asm volatile(
        "mma.sync.aligned.m16n8k8.row.col.f32.tf32.tf32.f32 "
        "{%0,%1,%2,%3}, {%4,%5,%6,%7}, {%8,%9}, {%0,%1,%2,%3};"
        : "+f"(c[0]), "+f"(c[1]), "+f"(c[2]), "+f"(c[3])
        : "r"(a0), "r"(a1), "r"(a2), "r"(a3), "r"(b0), "r"(b1));
}

__global__ __launch_bounds__(256, 1) void tf32_gemm_kernel(
    const float* __restrict__ A, const float* __restrict__ B,
    const float* __restrict__ bias, float* __restrict__ C,
    float alpha)
{
    extern __shared__ unsigned gsm[];
    // As[buf] = gsm + buf*BUF;  Bs[buf] = gsm + 2*BUF + buf*BUF
    unsigned* const AsBase = gsm;
    unsigned* const BsBase = gsm + 2 * GEMM_BUF_WORDS;

    const int tid  = threadIdx.x;
    const int lane = tid & 31;
    const int wid  = tid >> 5;
    const int gid  = lane >> 2;   // group id 0..7
    const int tg   = lane & 3;    // thread-in-group 0..3

    const int warp_m = wid & 1;           // 0..1
    const int warp_n = wid >> 1;          // 0..3
    const int mb = warp_m * 64;
    const int nb = warp_n * 32;

    const int bx = blockIdx.x;            // N tile
    const int by = blockIdx.y;            // M tile

    const float* Ab = A + (size_t)by * GBM * DIM;     // K == DIM == 1024
    const float* Bb = B + (size_t)bx * GBN;

    // global-load mapping
    const int a_row = tid & 127;          // A row within tile
    const int a_cb  = (tid >> 7) * 16;    // A col base: 0 or 16 (+ c*4)
    const int b_row = tid >> 3;           // B k-row within tile 0..31
    const int b_cb  = (tid & 7) * 4;      // B col base (+ c*32)

    float acc[4][4][4];
    #pragma unroll
    for (int t = 0; t < 4; t++)
        #pragma unroll
        for (int u = 0; u < 4; u++)
            #pragma unroll
            for (int r = 0; r < 4; r++)
                acc[t][u][r] = 0.f;

    float4 pa[4], pb[4];

    // ---- preload tile 0 ----
    #pragma unroll
    for (int c = 0; c < 4; c++) {
        pa[c] = *(const float4*)(Ab + (size_t)a_row * DIM + a_cb + c * 4);
        pb[c] = *(const float4*)(Bb + (size_t)b_row * DIM + b_cb + c * 32);
    }
    {
        unsigned* As0 = AsBase;
        unsigned* Bs0 = BsBase;
        #pragma unroll
        for (int c = 0; c < 4; c++) {
            const int ac = a_cb + c * 4;
            As0[(ac + 0) * GSTR + a_row] = f2tf32(pa[c].x);
            As0[(ac + 1) * GSTR + a_row] = f2tf32(pa[c].y);
            As0[(ac + 2) * GSTR + a_row] = f2tf32(pa[c].z);
            As0[(ac + 3) * GSTR + a_row] = f2tf32(pa[c].w);
            uint4 bv;
            bv.x = f2tf32(pb[c].x); bv.y = f2tf32(pb[c].y);
            bv.z = f2tf32(pb[c].z); bv.w = f2tf32(pb[c].w);
            *(uint4*)(&Bs0[b_row * GSTR + b_cb + c * 32]) = bv;
        }
    }
    __syncthreads();

    const int NT = DIM / GBK;     // 32 tiles
    int cur = 0;
    for (int t0 = 0; t0 < NT; t0++) {
        const bool has_next = (t0 + 1) < NT;
        if (has_next) {
            const int kn = (t0 + 1) * GBK;
            #pragma unroll
            for (int c = 0; c < 4; c++) {
                pa[c] = *(const float4*)(Ab + (size_t)a_row * DIM + kn + a_cb + c * 4);
                pb[c] = *(const float4*)(Bb + (size_t)(kn + b_row) * DIM + b_cb + c * 32);
            }
        }

        // ---- compute: 4 k8-steps over this tile ----
        const unsigned* Asc = AsBase + cur * GEMM_BUF_WORDS;
        const unsigned* Bsc = BsBase + cur * GEMM_BUF_WORDS;
        #pragma unroll
        for (int kb = 0; kb < GBK; kb += 8) {
            unsigned af0[4], af1[4], af2[4], af3[4], bf0[4], bf1[4];
            #pragma unroll
            for (int t = 0; t < 4; t++) {
                const int m0 = mb + t * 16 + gid;
                af0[t] = Asc[(kb + tg    ) * GSTR + m0];
                af1[t] = Asc[(kb + tg    ) * GSTR + m0 + 8];
                af2[t] = Asc[(kb + tg + 4) * GSTR + m0];
                af3[t] = Asc[(kb + tg + 4) * GSTR + m0 + 8];
            }
            #pragma unroll
            for (int u = 0; u < 4; u++) {
                const int n0 = nb + u * 8 + gid;
                bf0[u] = Bsc[(kb + tg    ) * GSTR + n0];
                bf1[u] = Bsc[(kb + tg + 4) * GSTR + n0];
            }
            #pragma unroll
            for (int t = 0; t < 4; t++)
                #pragma unroll
                for (int u = 0; u < 4; u++)
                    mma_tf32(acc[t][u], af0[t], af1[t], af2[t], af3[t],
                             bf0[u], bf1[u]);
        }

        if (has_next) {
            const int nxt = cur ^ 1;
            unsigned* Asn = AsBase + nxt * GEMM_BUF_WORDS;
            unsigned* Bsn = BsBase + nxt * GEMM_BUF_WORDS;
            #pragma unroll
            for (int c = 0; c < 4; c++) {
                const int ac = a_cb + c * 4;
                Asn[(ac + 0) * GSTR + a_row] = f2tf32(pa[c].x);
                Asn[(ac + 1) * GSTR + a_row] = f2tf32(pa[c].y);
                Asn[(ac + 2) * GSTR + a_row] = f2tf32(pa[c].z);
                Asn[(ac + 3) * GSTR + a_row] = f2tf32(pa[c].w);
                uint4 bv;
                bv.x = f2tf32(pb[c].x); bv.y = f2tf32(pb[c].y);
                bv.z = f2tf32(pb[c].z); bv.w = f2tf32(pb[c].w);
                *(uint4*)(&Bsn[b_row * GSTR + b_cb + c * 32]) = bv;
            }
            cur = nxt;
            __syncthreads();
        }
    }

    // ---- epilogue: alpha * (acc + bias) ----
    #pragma unroll
    for (int t = 0; t < 4; t++) {
        const int row0 = by * GBM + mb + t * 16 + gid;
        #pragma unroll
        for (int u = 0; u < 4; u++) {
            const int col = bx * GBN + nb + u * 8 + tg * 2;
            const float2 bv = *(const float2*)(bias + col);
            float2 c0, c1;
            c0.x = alpha * (acc[t][u][0] + bv.x);
            c0.y = alpha * (acc[t][u][1] + bv.y);
            c1.x = alpha * (acc[t][u][2] + bv.x);
            c1.y = alpha * (acc[t][u][3] + bv.y);
            *(float2*)(C + (size_t)row0 * DIM + col)       = c0;
            *(float2*)(C + (size_t)(row0 + 8) * DIM + col) = c1;
        }
    }
}

// ---------------------------------------------------------------------------
// Flash attention v2 (block-cooperative, SGEMM-style register tiling).
// softmax(s)*g / sum(softmax(s)*g) == exp(s-m)*g / sum(exp(s-m)*g):
// gauss weight folds into online-softmax weights.
//
// Block: 128 queries x one head. 256 threads as (ty,tx)=(16,16).
// Each thread: 8 query rows x 4 key cols / 4 output dims.
// Tiles of 64 keys. Q and K transposed in smem (d-major); P staged via smem.
// ---------------------------------------------------------------------------
#define BQ   128
#define BKT  64
#define KSTR 68     // padded k/v row stride (floats)
#define PSTR 132    // padded P row stride (floats)

#define QS_OFF 0                       // Qs[64][128]   (d-major)
#define KS_OFF 8192                    // Ks[64][68]    (d-major)
#define VS_OFF (KS_OFF + 64*KSTR)      // Vs[64][68]    (k-major, natural)
#define PS_OFF (VS_OFF + 64*KSTR)      // Ps[64][132]   (k-major)
#define GS_OFF (PS_OFF + 64*PSTR)      // Gs[64]
#define FSMEM_FLOATS (GS_OFF + 64)
#define FSMEM_BYTES  (FSMEM_FLOATS * 4)

__global__ __launch_bounds__(256, 2) void flash_attn2_kernel(
    const int* __restrict__ mask, const float* __restrict__ gauss)
{
    extern __shared__ float sm[];
    float* Qs = sm + QS_OFF;
    float* Ks = sm + KS_OFF;
    float* Vs = sm + VS_OFF;
    float* Ps = sm + PS_OFF;
    float* Gs = sm + GS_OFF;

    const int tid = threadIdx.x;
    const int tx  = tid & 15;
    const int ty  = tid >> 4;
    const int b   = blockIdx.z;
    const int h   = blockIdx.y;
    const int qbase = blockIdx.x * BQ;

    // ---- load Q block transposed into Qs[d][q] (once) ----
    {
        const float* qg = g_q + ((size_t)(b * SEQ + qbase)) * DIM + h * D_HEAD;
        #pragma unroll
        for (int c = 0; c < 8; c++) {
            int flat = (c * 256 + tid) * 4;       // 8192 floats total
            int qr = flat >> 6;                    // 0..127
            int d  = flat & 63;
            float4 v = *(const float4*)(qg + (size_t)qr * DIM + d);
            Qs[(d + 0) * 128 + qr] = v.x;
            Qs[(d + 1) * 128 + qr] = v.y;
            Qs[(d + 2) * 128 + qr] = v.z;
            Qs[(d + 3) * 128 + qr] = v.w;
        }
    }

    float m[8], l[8], O[8][4];
    #pragma unroll
    for (int i = 0; i < 8; i++) {
        m[i] = -1e30f; l[i] = 0.f;
        #pragma unroll
        for (int j = 0; j < 4; j++) O[i][j] = 0.f;
    }

    for (int kt = 0; kt < SEQ; kt += BKT) {
        // ---- load tile: K transposed (d-major), V natural (k-major) ----
        {
            const float* kg = g_k + ((size_t)(b * SEQ + kt)) * DIM + h * D_HEAD;
            const float* vg = g_v + ((size_t)(b * SEQ + kt)) * DIM + h * D_HEAD;
            #pragma unroll
            for (int c = 0; c < 4; c++) {
                int flat = (c * 256 + tid) * 4;    // 4096 floats total
                int kr = flat >> 6;                 // 0..63
                int d  = flat & 63;
                float4 kv = *(const float4*)(kg + (size_t)kr * DIM + d);
                Ks[(d + 0) * KSTR + kr] = kv.x;
                Ks[(d + 1) * KSTR + kr] = kv.y;
                Ks[(d + 2) * KSTR + kr] = kv.z;
                Ks[(d + 3) * KSTR + kr] = kv.w;
                *(float4*)(Vs + (size_t)kr * KSTR + d) =
                    *(const float4*)(vg + (size_t)kr * DIM + d);
            }
            if (tid < BKT) {
                int kk = kt + tid;
                float g = gauss[b * SEQ + kk] + 1e-10f;
                Gs[tid] = (mask[b * SEQ + kk] == 0) ? 0.f : g;
            }
        }
        __syncthreads();

        // ---- S = Q · Kt  (reduction over d) ----
        float S[8][4];
        #pragma unroll
        for (int i = 0; i < 8; i++)
            #pragma unroll
            for (int j = 0; j < 4; j++) S[i][j] = 0.f;

        #pragma unroll 8
        for (int kk = 0; kk < D_HEAD; kk++) {
            float4 a0 = *(const float4*)(Qs + kk * 128 + ty * 8);
            float4 a1 = *(const float4*)(Qs + kk * 128 + ty * 8 + 4);
            float4 bb = *(const float4*)(Ks + kk * KSTR + tx * 4);
            float a_frag[8] = {a0.x, a0.y, a0.z, a0.w, a1.x, a1.y, a1.z, a1.w};
            float b_frag[4] = {bb.x, bb.y, bb.z, bb.w};
            #pragma unroll
            for (int i = 0; i < 8; i++)
                #pragma unroll
                for (int j = 0; j < 4; j++)
                    S[i][j] = fmaf(a_frag[i], b_frag[j], S[i][j]);
        }

        // ---- online softmax with gauss fold ----
        float g4[4];
        #pragma unroll
        for (int j = 0; j < 4; j++) g4[j] = Gs[tx * 4 + j];

        #pragma unroll
        for (int i = 0; i < 8; i++) {
            float eff[4];
            float lm = -1e30f;
            #pragma unroll
            for (int j = 0; j < 4; j++) {
                eff[j] = (g4[j] > 0.f) ? S[i][j] : -1e30f;
                lm = fmaxf(lm, eff[j]);
            }
            // max over the 16 lanes sharing this row block
            #pragma unroll
            for (int off = 8; off >= 1; off >>= 1)
                lm = fmaxf(lm, __shfl_xor_sync(0xffffffffu, lm, off));

            float mnew  = fmaxf(m[i], lm);
            float scale = __expf(m[i] - mnew);
            float rs = 0.f;
            #pragma unroll
            for (int j = 0; j < 4; j++) {
                float p = g4[j] * __expf(eff[j] - mnew);
                S[i][j] = p;          // S now holds P
                rs += p;
            }
            #pragma unroll
            for (int off = 8; off >= 1; off >>= 1)
                rs += __shfl_xor_sync(0xffffffffu, rs, off);

            l[i] = l[i] * scale + rs;
            m[i] = mnew;
            #pragma unroll
            for (int j = 0; j < 4; j++) O[i][j] *= scale;
        }

        // ---- write P transposed: Ps[k][q] ----
        #pragma unroll
        for (int j = 0; j < 4; j++) {
            float4 v0 = make_float4(S[0][j], S[1][j], S[2][j], S[3][j]);
            float4 v1 = make_float4(S[4][j], S[5][j], S[6][j], S[7][j]);
            *(float4*)(Ps + (tx * 4 + j) * PSTR + ty * 8)     = v0;
            *(float4*)(Ps + (tx * 4 + j) * PSTR + ty * 8 + 4) = v1;
        }
        __syncthreads();

        // ---- O += P · V  (reduction over keys) ----
        #pragma unroll 8
        for (int kk = 0; kk < BKT; kk++) {
            float4 a0 = *(const float4*)(Ps + kk * PSTR + ty * 8);
            float4 a1 = *(const float4*)(Ps + kk * PSTR + ty * 8 + 4);
            float4 bb = *(const float4*)(Vs + kk * KSTR + tx * 4);
            float a_frag[8] = {a0.x, a0.y, a0.z, a0.w, a1.x, a1.y, a1.z, a1.w};
            float b_frag[4] = {bb.x, bb.y, bb.z, bb.w};
            #pragma unroll
            for (int i = 0; i < 8; i++)
                #pragma unroll
                for (int j = 0; j < 4; j++)
                    O[i][j] = fmaf(a_frag[i], b_frag[j], O[i][j]);
        }
        __syncthreads();
    }

    // ---- epilogue ----
    #pragma unroll
    for (int i = 0; i < 8; i++) {
        float inv = 1.f / l[i];
        float4 ov = make_float4(O[i][0] * inv, O[i][1] * inv,
                                O[i][2] * inv, O[i][3] * inv);
        int row = qbase + ty * 8 + i;
        *(float4*)(g_ctx + ((size_t)(b * SEQ + row)) * DIM + h * D_HEAD + tx * 4) = ov;
    }
}

// ---------------------------------------------------------------------------
// Launch
// inputs: 0=query 1=key 2=value 3=mask 4=gauss_weight
//         5=Wq 6=bq 7=Wk 8=bk 9=Wv 10=bv 11=Wo 12=bo
// ---------------------------------------------------------------------------
extern "C" void kernel_launch(void* const* d_in, const int* in_sizes, int n_in,
                              void* d_out, int out_size)
{
    const float* query = (const float*)d_in[0];
    const float* key   = (const float*)d_in[1];
    const float* value = (const float*)d_in[2];
    const int*   mask  = (const int*)  d_in[3];
    const float* gauss = (const float*)d_in[4];
    const float* Wq = (const float*)d_in[5];
    const float* bq = (const float*)d_in[6];
    const float* Wk = (const float*)d_in[7];
    const float* bk = (const float*)d_in[8];
    const float* Wv = (const float*)d_in[9];
    const float* bv = (const float*)d_in[10];
    const float* Wo = (const float*)d_in[11];
    const float* bo = (const float*)d_in[12];
    float* out = (float*)d_out;

    float *pq, *pk, *pv, *pctx;
    cudaGetSymbolAddress((void**)&pq,   g_q);
    cudaGetSymbolAddress((void**)&pk,   g_k);
    cudaGetSymbolAddress((void**)&pv,   g_v);
    cudaGetSymbolAddress((void**)&pctx, g_ctx);

    // allow >48KB dynamic smem (idempotent host calls, not stream ops ->
    // safe under graph capture)
    cudaFuncSetAttribute(tf32_gemm_kernel,
                         cudaFuncAttributeMaxDynamicSharedMemorySize,
                         GEMM_SMEM_BYTES);
    cudaFuncSetAttribute(flash_attn2_kernel,
                         cudaFuncAttributeMaxDynamicSharedMemorySize,
                         FSMEM_BYTES);

    dim3 ggrid(DIM / GBN, MROWS / GBM);   // (8, 32)
    const float qscale = 1.0f / 8.0f;     // 1/sqrt(D_HEAD)

    tf32_gemm_kernel<<<ggrid, 256, GEMM_SMEM_BYTES>>>(query, Wq, bq, pq, qscale);
    tf32_gemm_kernel<<<ggrid, 256, GEMM_SMEM_BYTES>>>(key,   Wk, bk, pk, 1.0f);
    tf32_gemm_kernel<<<ggrid, 256, GEMM_SMEM_BYTES>>>(value, Wv, bv, pv, 1.0f);

    dim3 agrid(SEQ / BQ, N_HEADS, BS);    // (8, 16, 4)
    flash_attn2_kernel<<<agrid, 256, FSMEM_BYTES>>>(mask, gauss);

    tf32_gemm_kernel<<<ggrid, 256, GEMM_SMEM_BYTES>>>(pctx, Wo, bo, out, 1.0f);
}

// round 8
// speedup vs baseline: 1.7350x; 1.0587x over previous
#include <cuda_runtime.h>
#include <cuda_bf16.h>
#include <math.h>

// Problem constants
#define BS      4
#define SEQ     1024
#define DIM     1024
#define N_HEADS 16
#define D_HEAD  64
#define MROWS   (BS * SEQ)      // 4096

// ---------------------------------------------------------------------------
// Scratch (static device globals; no runtime allocation allowed)
// ---------------------------------------------------------------------------
__device__ float g_q  [MROWS * DIM];
__device__ float g_k  [MROWS * DIM];
__device__ float g_v  [MROWS * DIM];
__device__ float g_ctx[MROWS * DIM];

// ---------------------------------------------------------------------------
// TF32 tensor-core GEMM: C = alpha * (A @ B + bias)
// A: MxK row-major, B: KxN row-major (N = DIM), bias: N
// Block tile 256x128, BK=16, 512 threads = 16 warps (4x4), warp tile 64x32.
// Grid = (1024/128) x (4096/256) = 8 x 16 = 128 blocks -> single wave on 148
// SMs (no wave-quantization tail), 16 warps/SM for issue-latency hiding.
// mma.sync.aligned.m16n8k8.row.col.f32.tf32.tf32.f32
// Smem (dynamic, 51200B): As[2][16][264], Bs[2][16][136]
//   (264 % 32 == 8, 136 % 32 == 8 -> conflict-free fragment loads).
// ---------------------------------------------------------------------------
#define GBM 256
#define GBN 128
#define GBK 16
#define ASTR 264
#define BSTR 136
#define GEMM_A_BUF (GBK * ASTR)                     // 4224 words / buffer
#define GEMM_B_BUF (GBK * BSTR)                     // 2176 words / buffer
#define GEMM_SMEM_WORDS (2 * GEMM_A_BUF + 2 * GEMM_B_BUF)   // 12800
#define GEMM_SMEM_BYTES (GEMM_SMEM_WORDS * 4)               // 51200

__device__ __forceinline__ unsigned f2tf32(float f) {
    unsigned u;
    asm("cvt.rna.tf32.f32 %0, %1;" : "=r"(u) : "f"(f));
    return u;
}

__device__ __forceinline__ void mma_tf32(float c[4],
    unsigned a0, unsigned a1, unsigned a2, unsigned a3,
    unsigned b0, unsigned b1)
{
    asm volatile(
        "mma.sync.aligned.m16n8k8.row.col.f32.tf32.tf32.f32 "
        "{%0,%1,%2,%3}, {%4,%5,%6,%7}, {%8,%9}, {%0,%1,%2,%3};"
        : "+f"(c[0]), "+f"(c[1]), "+f"(c[2]), "+f"(c[3])
        : "r"(a0), "r"(a1), "r"(a2), "r"(a3), "r"(b0), "r"(b1));
}

__global__ __launch_bounds__(512, 1) void tf32_gemm_kernel(
    const float* __restrict__ A, const float* __restrict__ B,
    const float* __restrict__ bias, float* __restrict__ C,
    float alpha)
{
    extern __shared__ unsigned gsm[];
    unsigned* const AsBase = gsm;                        // 2 x GEMM_A_BUF
    unsigned* const BsBase = gsm + 2 * GEMM_A_BUF;       // 2 x GEMM_B_BUF

    const int tid  = threadIdx.x;
    const int lane = tid & 31;
    const int wid  = tid >> 5;        // 0..15
    const int gid  = lane >> 2;       // 0..7
    const int tg   = lane & 3;        // 0..3

    const int warp_m = wid & 3;       // 0..3
    const int warp_n = wid >> 2;      // 0..3
    const int mb = warp_m * 64;
    const int nb = warp_n * 32;

    const int bx = blockIdx.x;        // N tile
    const int by = blockIdx.y;        // M tile

    const float* Ab = A + (size_t)by * GBM * DIM;    // K == DIM == 1024
    const float* Bb = B + (size_t)bx * GBN;

    // global-load mapping
    // A tile: 256 rows x 16 cols = 4096 words -> 2 float4 / thread
    const int a_row = tid & 255;              // 0..255
    const int a_cb  = (tid >> 8) * 8;         // 0 or 8  (float4 at +0, +4)
    // B tile: 16 rows x 128 cols = 2048 words -> 1 float4 / thread
    const int b_row = tid >> 5;               // 0..15
    const int b_col = (tid & 31) * 4;         // 0..124

    float acc[4][4][4];
    #pragma unroll
    for (int t = 0; t < 4; t++)
        #pragma unroll
        for (int u = 0; u < 4; u++)
            #pragma unroll
            for (int r = 0; r < 4; r++)
                acc[t][u][r] = 0.f;

    float4 pa0, pa1, pb0;

    // ---- preload tile 0 ----
    pa0 = *(const float4*)(Ab + (size_t)a_row * DIM + a_cb);
    pa1 = *(const float4*)(Ab + (size_t)a_row * DIM + a_cb + 4);
    pb0 = *(const float4*)(Bb + (size_t)b_row * DIM + b_col);
    {
        unsigned* As0 = AsBase;
        unsigned* Bs0 = BsBase;
        As0[(a_cb + 0) * ASTR + a_row] = f2tf32(pa0.x);
        As0[(a_cb + 1) * ASTR + a_row] = f2tf32(pa0.y);
        As0[(a_cb + 2) * ASTR + a_row] = f2tf32(pa0.z);
        As0[(a_cb + 3) * ASTR + a_row] = f2tf32(pa0.w);
        As0[(a_cb + 4) * ASTR + a_row] = f2tf32(pa1.x);
        As0[(a_cb + 5) * ASTR + a_row] = f2tf32(pa1.y);
        As0[(a_cb + 6) * ASTR + a_row] = f2tf32(pa1.z);
        As0[(a_cb + 7) * ASTR + a_row] = f2tf32(pa1.w);
        uint4 bv;
        bv.x = f2tf32(pb0.x); bv.y = f2tf32(pb0.y);
        bv.z = f2tf32(pb0.z); bv.w = f2tf32(pb0.w);
        *(uint4*)(&Bs0[b_row * BSTR + b_col]) = bv;
    }
    __syncthreads();

    const int NT = DIM / GBK;     // 64 tiles
    int cur = 0;
    for (int t0 = 0; t0 < NT; t0++) {
        const bool has_next = (t0 + 1) < NT;
        if (has_next) {
            const int kn = (t0 + 1) * GBK;
            pa0 = *(const float4*)(Ab + (size_t)a_row * DIM + kn + a_cb);
            pa1 = *(const float4*)(Ab + (size_t)a_row * DIM + kn + a_cb + 4);
            pb0 = *(const float4*)(Bb + (size_t)(kn + b_row) * DIM + b_col);
        }

        // ---- compute: 2 k8-steps over this tile ----
        const unsigned* Asc = AsBase + cur * GEMM_A_BUF;
        const unsigned* Bsc = BsBase + cur * GEMM_B_BUF;
        #pragma unroll
        for (int kb = 0; kb < GBK; kb += 8) {
            unsigned af0[4], af1[4], af2[4], af3[4], bf0[4], bf1[4];
            #pragma unroll
            for (int t = 0; t < 4; t++) {
                const int m0 = mb + t * 16 + gid;
                af0[t] = Asc[(kb + tg    ) * ASTR + m0];
                af1[t] = Asc[(kb + tg    ) * ASTR + m0 + 8];
                af2[t] = Asc[(kb + tg + 4) * ASTR + m0];
                af3[t] = Asc[(kb + tg + 4) * ASTR + m0 + 8];
            }
            #pragma unroll
            for (int u = 0; u < 4; u++) {
                const int n0 = nb + u * 8 + gid;
                bf0[u] = Bsc[(kb + tg    ) * BSTR + n0];
                bf1[u] = Bsc[(kb + tg + 4) * BSTR + n0];
            }
            #pragma unroll
            for (int t = 0; t < 4; t++)
                #pragma unroll
                for (int u = 0; u < 4; u++)
                    mma_tf32(acc[t][u], af0[t], af1[t], af2[t], af3[t],
                             bf0[u], bf1[u]);
        }

        if (has_next) {
            const int nxt = cur ^ 1;
            unsigned* Asn = AsBase + nxt * GEMM_A_BUF;
            unsigned* Bsn = BsBase + nxt * GEMM_B_BUF;
            Asn[(a_cb + 0) * ASTR + a_row] = f2tf32(pa0.x);
            Asn[(a_cb + 1) * ASTR + a_row] = f2tf32(pa0.y);
            Asn[(a_cb + 2) * ASTR + a_row] = f2tf32(pa0.z);
            Asn[(a_cb + 3) * ASTR + a_row] = f2tf32(pa0.w);
            Asn[(a_cb + 4) * ASTR + a_row] = f2tf32(pa1.x);
            Asn[(a_cb + 5) * ASTR + a_row] = f2tf32(pa1.y);
            Asn[(a_cb + 6) * ASTR + a_row] = f2tf32(pa1.z);
            Asn[(a_cb + 7) * ASTR + a_row] = f2tf32(pa1.w);
            uint4 bv;
            bv.x = f2tf32(pb0.x); bv.y = f2tf32(pb0.y);
            bv.z = f2tf32(pb0.z); bv.w = f2tf32(pb0.w);
            *(uint4*)(&Bsn[b_row * BSTR + b_col]) = bv;
            cur = nxt;
            __syncthreads();
        }
    }

    // ---- epilogue: alpha * (acc + bias) ----
    #pragma unroll
    for (int t = 0; t < 4; t++) {
        const int row0 = by * GBM + mb + t * 16 + gid;
        #pragma unroll
        for (int u = 0; u < 4; u++) {
            const int col = bx * GBN + nb + u * 8 + tg * 2;
            const float2 bv = *(const float2*)(bias + col);
            float2 c0, c1;
            c0.x = alpha * (acc[t][u][0] + bv.x);
            c0.y = alpha * (acc[t][u][1] + bv.y);
            c1.x = alpha * (acc[t][u][2] + bv.x);
            c1.y = alpha * (acc[t][u][3] + bv.y);
            *(float2*)(C + (size_t)row0 * DIM + col)       = c0;
            *(float2*)(C + (size_t)(row0 + 8) * DIM + col) = c1;
        }
    }
}

// ---------------------------------------------------------------------------
// Flash attention v2 (block-cooperative, SGEMM-style register tiling).
// softmax(s)*g / sum(softmax(s)*g) == exp(s-m)*g / sum(exp(s-m)*g):
// gauss weight folds into online-softmax weights.
//
// Block: 128 queries x one head. 256 threads as (ty,tx)=(16,16).
// Each thread: 8 query rows x 4 key cols / 4 output dims.
// Tiles of 64 keys. Q and K transposed in smem (d-major); P staged via smem.
// (unchanged from the 952us round — GEMM is this round's isolated variable)
// ---------------------------------------------------------------------------
#define BQ   128
#define BKT  64
#define KSTR 68     // padded k/v row stride (floats)
#define PSTR 132    // padded P row stride (floats)

#define QS_OFF 0                       // Qs[64][128]   (d-major)
#define KS_OFF 8192                    // Ks[64][68]    (d-major)
#define VS_OFF (KS_OFF + 64*KSTR)      // Vs[64][68]    (k-major, natural)
#define PS_OFF (VS_OFF + 64*KSTR)      // Ps[64][132]   (k-major)
#define GS_OFF (PS_OFF + 64*PSTR)      // Gs[64]
#define FSMEM_FLOATS (GS_OFF + 64)
#define FSMEM_BYTES  (FSMEM_FLOATS * 4)

__global__ __launch_bounds__(256, 2) void flash_attn2_kernel(
    const int* __restrict__ mask, const float* __restrict__ gauss)
{
    extern __shared__ float sm[];
    float* Qs = sm + QS_OFF;
    float* Ks = sm + KS_OFF;
    float* Vs = sm + VS_OFF;
    float* Ps = sm + PS_OFF;
    float* Gs = sm + GS_OFF;

    const int tid = threadIdx.x;
    const int tx  = tid & 15;
    const int ty  = tid >> 4;
    const int b   = blockIdx.z;
    const int h   = blockIdx.y;
    const int qbase = blockIdx.x * BQ;

    // ---- load Q block transposed into Qs[d][q] (once) ----
    {
        const float* qg = g_q + ((size_t)(b * SEQ + qbase)) * DIM + h * D_HEAD;
        #pragma unroll
        for (int c = 0; c < 8; c++) {
            int flat = (c * 256 + tid) * 4;       // 8192 floats total
            int qr = flat >> 6;                    // 0..127
            int d  = flat & 63;
            float4 v = *(const float4*)(qg + (size_t)qr * DIM + d);
            Qs[(d + 0) * 128 + qr] = v.x;
            Qs[(d + 1) * 128 + qr] = v.y;
            Qs[(d + 2) * 128 + qr] = v.z;
            Qs[(d + 3) * 128 + qr] = v.w;
        }
    }

    float m[8], l[8], O[8][4];
    #pragma unroll
    for (int i = 0; i < 8; i++) {
        m[i] = -1e30f; l[i] = 0.f;
        #pragma unroll
        for (int j = 0; j < 4; j++) O[i][j] = 0.f;
    }

    for (int kt = 0; kt < SEQ; kt += BKT) {
        // ---- load tile: K transposed (d-major), V natural (k-major) ----
        {
            const float* kg = g_k + ((size_t)(b * SEQ + kt)) * DIM + h * D_HEAD;
            const float* vg = g_v + ((size_t)(b * SEQ + kt)) * DIM + h * D_HEAD;
            #pragma unroll
            for (int c = 0; c < 4; c++) {
                int flat = (c * 256 + tid) * 4;    // 4096 floats total
                int kr = flat >> 6;                 // 0..63
                int d  = flat & 63;
                float4 kv = *(const float4*)(kg + (size_t)kr * DIM + d);
                Ks[(d + 0) * KSTR + kr] = kv.x;
                Ks[(d + 1) * KSTR + kr] = kv.y;
                Ks[(d + 2) * KSTR + kr] = kv.z;
                Ks[(d + 3) * KSTR + kr] = kv.w;
                *(float4*)(Vs + (size_t)kr * KSTR + d) =
                    *(const float4*)(vg + (size_t)kr * DIM + d);
            }
            if (tid < BKT) {
                int kk = kt + tid;
                float g = gauss[b * SEQ + kk] + 1e-10f;
                Gs[tid] = (mask[b * SEQ + kk] == 0) ? 0.f : g;
            }
        }
        __syncthreads();

        // ---- S = Q · Kt  (reduction over d) ----
        float S[8][4];
        #pragma unroll
        for (int i = 0; i < 8; i++)
            #pragma unroll
            for (int j = 0; j < 4; j++) S[i][j] = 0.f;

        #pragma unroll 8
        for (int kk = 0; kk < D_HEAD; kk++) {
            float4 a0 = *(const float4*)(Qs + kk * 128 + ty * 8);
            float4 a1 = *(const float4*)(Qs + kk * 128 + ty * 8 + 4);
            float4 bb = *(const float4*)(Ks + kk * KSTR + tx * 4);
            float a_frag[8] = {a0.x, a0.y, a0.z, a0.w, a1.x, a1.y, a1.z, a1.w};
            float b_frag[4] = {bb.x, bb.y, bb.z, bb.w};
            #pragma unroll
            for (int i = 0; i < 8; i++)
                #pragma unroll
                for (int j = 0; j < 4; j++)
                    S[i][j] = fmaf(a_frag[i], b_frag[j], S[i][j]);
        }

        // ---- online softmax with gauss fold ----
        float g4[4];
        #pragma unroll
        for (int j = 0; j < 4; j++) g4[j] = Gs[tx * 4 + j];

        #pragma unroll
        for (int i = 0; i < 8; i++) {
            float eff[4];
            float lm = -1e30f;
            #pragma unroll
            for (int j = 0; j < 4; j++) {
                eff[j] = (g4[j] > 0.f) ? S[i][j] : -1e30f;
                lm = fmaxf(lm, eff[j]);
            }
            // max over the 16 lanes sharing this row block
            #pragma unroll
            for (int off = 8; off >= 1; off >>= 1)
                lm = fmaxf(lm, __shfl_xor_sync(0xffffffffu, lm, off));

            float mnew  = fmaxf(m[i], lm);
            float scale = __expf(m[i] - mnew);
            float rs = 0.f;
            #pragma unroll
            for (int j = 0; j < 4; j++) {
                float p = g4[j] * __expf(eff[j] - mnew);
                S[i][j] = p;          // S now holds P
                rs += p;
            }
            #pragma unroll
            for (int off = 8; off >= 1; off >>= 1)
                rs += __shfl_xor_sync(0xffffffffu, rs, off);

            l[i] = l[i] * scale + rs;
            m[i] = mnew;
            #pragma unroll
            for (int j = 0; j < 4; j++) O[i][j] *= scale;
        }

        // ---- write P transposed: Ps[k][q] ----
        #pragma unroll
        for (int j = 0; j < 4; j++) {
            float4 v0 = make_float4(S[0][j], S[1][j], S[2][j], S[3][j]);
            float4 v1 = make_float4(S[4][j], S[5][j], S[6][j], S[7][j]);
            *(float4*)(Ps + (tx * 4 + j) * PSTR + ty * 8)     = v0;
            *(float4*)(Ps + (tx * 4 + j) * PSTR + ty * 8 + 4) = v1;
        }
        __syncthreads();

        // ---- O += P · V  (reduction over keys) ----
        #pragma unroll 8
        for (int kk = 0; kk < BKT; kk++) {
            float4 a0 = *(const float4*)(Ps + kk * PSTR + ty * 8);
            float4 a1 = *(const float4*)(Ps + kk * PSTR + ty * 8 + 4);
            float4 bb = *(const float4*)(Vs + kk * KSTR + tx * 4);
            float a_frag[8] = {a0.x, a0.y, a0.z, a0.w, a1.x, a1.y, a1.z, a1.w};
            float b_frag[4] = {bb.x, bb.y, bb.z, bb.w};
            #pragma unroll
            for (int i = 0; i < 8; i++)
                #pragma unroll
                for (int j = 0; j < 4; j++)
                    O[i][j] = fmaf(a_frag[i], b_frag[j], O[i][j]);
        }
        __syncthreads();
    }

    // ---- epilogue ----
    #pragma unroll
    for (int i = 0; i < 8; i++) {
        float inv = 1.f / l[i];
        float4 ov = make_float4(O[i][0] * inv, O[i][1] * inv,
                                O[i][2] * inv, O[i][3] * inv);
        int row = qbase + ty * 8 + i;
        *(float4*)(g_ctx + ((size_t)(b * SEQ + row)) * DIM + h * D_HEAD + tx * 4) = ov;
    }
}

// ---------------------------------------------------------------------------
// Launch
// inputs: 0=query 1=key 2=value 3=mask 4=gauss_weight
//         5=Wq 6=bq 7=Wk 8=bk 9=Wv 10=bv 11=Wo 12=bo
// ---------------------------------------------------------------------------
extern "C" void kernel_launch(void* const* d_in, const int* in_sizes, int n_in,
                              void* d_out, int out_size)
{
    const float* query = (const float*)d_in[0];
    const float* key   = (const float*)d_in[1];
    const float* value = (const float*)d_in[2];
    const int*   mask  = (const int*)  d_in[3];
    const float* gauss = (const float*)d_in[4];
    const float* Wq = (const float*)d_in[5];
    const float* bq = (const float*)d_in[6];
    const float* Wk = (const float*)d_in[7];
    const float* bk = (const float*)d_in[8];
    const float* Wv = (const float*)d_in[9];
    const float* bv = (const float*)d_in[10];
    const float* Wo = (const float*)d_in[11];
    const float* bo = (const float*)d_in[12];
    float* out = (float*)d_out;

    float *pq, *pk, *pv, *pctx;
    cudaGetSymbolAddress((void**)&pq,   g_q);
    cudaGetSymbolAddress((void**)&pk,   g_k);
    cudaGetSymbolAddress((void**)&pv,   g_v);
    cudaGetSymbolAddress((void**)&pctx, g_ctx);

    // allow >48KB dynamic smem (idempotent host calls, not stream ops ->
    // safe under graph capture)
    cudaFuncSetAttribute(tf32_gemm_kernel,
                         cudaFuncAttributeMaxDynamicSharedMemorySize,
                         GEMM_SMEM_BYTES);
    cudaFuncSetAttribute(flash_attn2_kernel,
                         cudaFuncAttributeMaxDynamicSharedMemorySize,
                         FSMEM_BYTES);

    dim3 ggrid(DIM / GBN, MROWS / GBM);   // (8, 16) = 128 blocks
    const float qscale = 1.0f / 8.0f;     // 1/sqrt(D_HEAD)

    tf32_gemm_kernel<<<ggrid, 512, GEMM_SMEM_BYTES>>>(query, Wq, bq, pq, qscale);
    tf32_gemm_kernel<<<ggrid, 512, GEMM_SMEM_BYTES>>>(key,   Wk, bk, pk, 1.0f);
    tf32_gemm_kernel<<<ggrid, 512, GEMM_SMEM_BYTES>>>(value, Wv, bv, pv, 1.0f);

    dim3 agrid(SEQ / BQ, N_HEADS, BS);    // (8, 16, 4)
    flash_attn2_kernel<<<agrid, 256, FSMEM_BYTES>>>(mask, gauss);

    tf32_gemm_kernel<<<ggrid, 512, GEMM_SMEM_BYTES>>>(pctx, Wo, bo, out, 1.0f);
}

// round 9
// speedup vs baseline: 2.4904x; 1.4354x over previous
#include <cuda_runtime.h>
#include <cuda_bf16.h>
#include <math.h>

// Problem constants
#define BS      4
#define SEQ     1024
#define DIM     1024
#define N_HEADS 16
#define D_HEAD  64
#define MROWS   (BS * SEQ)      // 4096

// ---------------------------------------------------------------------------
// Scratch (static device globals; no runtime allocation allowed)
// ---------------------------------------------------------------------------
__device__ float g_q  [MROWS * DIM];
__device__ float g_k  [MROWS * DIM];
__device__ float g_v  [MROWS * DIM];
__device__ float g_ctx[MROWS * DIM];

// ---------------------------------------------------------------------------
// Common tf32 helpers
// ---------------------------------------------------------------------------
__device__ __forceinline__ unsigned f2tf32(float f) {
    unsigned u;
    asm("cvt.rna.tf32.f32 %0, %1;" : "=r"(u) : "f"(f));
    return u;
}

__device__ __forceinline__ void mma_tf32(float c[4],
    unsigned a0, unsigned a1, unsigned a2, unsigned a3,
    unsigned b0, unsigned b1)
{
    asm volatile(
        "mma.sync.aligned.m16n8k8.row.col.f32.tf32.tf32.f32 "
        "{%0,%1,%2,%3}, {%4,%5,%6,%7}, {%8,%9}, {%0,%1,%2,%3};"
        : "+f"(c[0]), "+f"(c[1]), "+f"(c[2]), "+f"(c[3])
        : "r"(a0), "r"(a1), "r"(a2), "r"(a3), "r"(b0), "r"(b1));
}

// Fast 2^x on the FMA/ALU pipes (no MUFU). Valid for x in [-100, 100];
// clamps outside. Rel err ~3e-6 (degree-5 Taylor on f in [-0.5, 0.5]).
#define LOG2E 1.4426950408889634f
__device__ __forceinline__ float fast_exp2(float x) {
    x = fminf(fmaxf(x, -100.0f), 100.0f);
    float z = x + 12582912.0f;                 // 1.5*2^23: round-to-nearest int
    int   n = __float_as_int(z) - 0x4B400000;  // n = round(x)
    float f = x - (z - 12582912.0f);           // f in [-0.5, 0.5]
    float p =            1.3333558e-3f;
    p = fmaf(p, f, 9.6181291e-3f);
    p = fmaf(p, f, 5.5504109e-2f);
    p = fmaf(p, f, 2.4022650e-1f);
    p = fmaf(p, f, 6.9314718e-1f);
    p = fmaf(p, f, 1.0f);                      // p in [0.707, 1.415)
    return __int_as_float(__float_as_int(p) + (n << 23));
}

// ---------------------------------------------------------------------------
// TF32 tensor-core GEMM: C = alpha * (A @ B + bias)   (unchanged from R8)
// Block tile 256x128, BK=16, 512 threads = 16 warps (4x4), warp tile 64x32.
// ---------------------------------------------------------------------------
#define GBM 256
#define GBN 128
#define GBK 16
#define ASTR 264
#define BSTR 136
#define GEMM_A_BUF (GBK * ASTR)
#define GEMM_B_BUF (GBK * BSTR)
#define GEMM_SMEM_WORDS (2 * GEMM_A_BUF + 2 * GEMM_B_BUF)
#define GEMM_SMEM_BYTES (GEMM_SMEM_WORDS * 4)       // 51200

__global__ __launch_bounds__(512, 1) void tf32_gemm_kernel(
    const float* __restrict__ A, const float* __restrict__ B,
    const float* __restrict__ bias, float* __restrict__ C,
    float alpha)
{
    extern __shared__ unsigned gsm[];
    unsigned* const AsBase = gsm;
    unsigned* const BsBase = gsm + 2 * GEMM_A_BUF;

    const int tid  = threadIdx.x;
    const int lane = tid & 31;
    const int wid  = tid >> 5;
    const int gid  = lane >> 2;
    const int tg   = lane & 3;

    const int warp_m = wid & 3;
    const int warp_n = wid >> 2;
    const int mb = warp_m * 64;
    const int nb = warp_n * 32;

    const int bx = blockIdx.x;
    const int by = blockIdx.y;

    const float* Ab = A + (size_t)by * GBM * DIM;
    const float* Bb = B + (size_t)bx * GBN;

    const int a_row = tid & 255;
    const int a_cb  = (tid >> 8) * 8;
    const int b_row = tid >> 5;
    const int b_col = (tid & 31) * 4;

    float acc[4][4][4];
    #pragma unroll
    for (int t = 0; t < 4; t++)
        #pragma unroll
        for (int u = 0; u < 4; u++)
            #pragma unroll
            for (int r = 0; r < 4; r++)
                acc[t][u][r] = 0.f;

    float4 pa0, pa1, pb0;

    pa0 = *(const float4*)(Ab + (size_t)a_row * DIM + a_cb);
    pa1 = *(const float4*)(Ab + (size_t)a_row * DIM + a_cb + 4);
    pb0 = *(const float4*)(Bb + (size_t)b_row * DIM + b_col);
    {
        unsigned* As0 = AsBase;
        unsigned* Bs0 = BsBase;
        As0[(a_cb + 0) * ASTR + a_row] = f2tf32(pa0.x);
        As0[(a_cb + 1) * ASTR + a_row] = f2tf32(pa0.y);
        As0[(a_cb + 2) * ASTR + a_row] = f2tf32(pa0.z);
        As0[(a_cb + 3) * ASTR + a_row] = f2tf32(pa0.w);
        As0[(a_cb + 4) * ASTR + a_row] = f2tf32(pa1.x);
        As0[(a_cb + 5) * ASTR + a_row] = f2tf32(pa1.y);
        As0[(a_cb + 6) * ASTR + a_row] = f2tf32(pa1.z);
        As0[(a_cb + 7) * ASTR + a_row] = f2tf32(pa1.w);
        uint4 bv;
        bv.x = f2tf32(pb0.x); bv.y = f2tf32(pb0.y);
        bv.z = f2tf32(pb0.z); bv.w = f2tf32(pb0.w);
        *(uint4*)(&Bs0[b_row * BSTR + b_col]) = bv;
    }
    __syncthreads();

    const int NT = DIM / GBK;
    int cur = 0;
    for (int t0 = 0; t0 < NT; t0++) {
        const bool has_next = (t0 + 1) < NT;
        if (has_next) {
            const int kn = (t0 + 1) * GBK;
            pa0 = *(const float4*)(Ab + (size_t)a_row * DIM + kn + a_cb);
            pa1 = *(const float4*)(Ab + (size_t)a_row * DIM + kn + a_cb + 4);
            pb0 = *(const float4*)(Bb + (size_t)(kn + b_row) * DIM + b_col);
        }

        const unsigned* Asc = AsBase + cur * GEMM_A_BUF;
        const unsigned* Bsc = BsBase + cur * GEMM_B_BUF;
        #pragma unroll
        for (int kb = 0; kb < GBK; kb += 8) {
            unsigned af0[4], af1[4], af2[4], af3[4], bf0[4], bf1[4];
            #pragma unroll
            for (int t = 0; t < 4; t++) {
                const int m0 = mb + t * 16 + gid;
                af0[t] = Asc[(kb + tg    ) * ASTR + m0];
                af1[t] = Asc[(kb + tg    ) * ASTR + m0 + 8];
                af2[t] = Asc[(kb + tg + 4) * ASTR + m0];
                af3[t] = Asc[(kb + tg + 4) * ASTR + m0 + 8];
            }
            #pragma unroll
            for (int u = 0; u < 4; u++) {
                const int n0 = nb + u * 8 + gid;
                bf0[u] = Bsc[(kb + tg    ) * BSTR + n0];
                bf1[u] = Bsc[(kb + tg + 4) * BSTR + n0];
            }
            #pragma unroll
            for (int t = 0; t < 4; t++)
                #pragma unroll
                for (int u = 0; u < 4; u++)
                    mma_tf32(acc[t][u], af0[t], af1[t], af2[t], af3[t],
                             bf0[u], bf1[u]);
        }

        if (has_next) {
            const int nxt = cur ^ 1;
            unsigned* Asn = AsBase + nxt * GEMM_A_BUF;
            unsigned* Bsn = BsBase + nxt * GEMM_B_BUF;
            Asn[(a_cb + 0) * ASTR + a_row] = f2tf32(pa0.x);
            Asn[(a_cb + 1) * ASTR + a_row] = f2tf32(pa0.y);
            Asn[(a_cb + 2) * ASTR + a_row] = f2tf32(pa0.z);
            Asn[(a_cb + 3) * ASTR + a_row] = f2tf32(pa0.w);
            Asn[(a_cb + 4) * ASTR + a_row] = f2tf32(pa1.x);
            Asn[(a_cb + 5) * ASTR + a_row] = f2tf32(pa1.y);
            Asn[(a_cb + 6) * ASTR + a_row] = f2tf32(pa1.z);
            Asn[(a_cb + 7) * ASTR + a_row] = f2tf32(pa1.w);
            uint4 bv;
            bv.x = f2tf32(pb0.x); bv.y = f2tf32(pb0.y);
            bv.z = f2tf32(pb0.z); bv.w = f2tf32(pb0.w);
            *(uint4*)(&Bsn[b_row * BSTR + b_col]) = bv;
            cur = nxt;
            __syncthreads();
        }
    }

    #pragma unroll
    for (int t = 0; t < 4; t++) {
        const int row0 = by * GBM + mb + t * 16 + gid;
        #pragma unroll
        for (int u = 0; u < 4; u++) {
            const int col = bx * GBN + nb + u * 8 + tg * 2;
            const float2 bv = *(const float2*)(bias + col);
            float2 c0, c1;
            c0.x = alpha * (acc[t][u][0] + bv.x);
            c0.y = alpha * (acc[t][u][1] + bv.y);
            c1.x = alpha * (acc[t][u][2] + bv.x);
            c1.y = alpha * (acc[t][u][3] + bv.y);
            *(float2*)(C + (size_t)row0 * DIM + col)       = c0;
            *(float2*)(C + (size_t)(row0 + 8) * DIM + col) = c1;
        }
    }
}

// ---------------------------------------------------------------------------
// Flash attention v3: tf32 tensor-core MMAs + FMA-pipe exp (no MUFU).
//
// softmax(s)*g / sum(softmax(s)*g) == 2^((s-m)log2e)*g / sum(...): gauss
// weight and mask fold into online-softmax weights; base-2 exp is exact
// reformulation.
//
// Block: 128 queries x one head, 256 threads = 8 warps.
// Warp w owns query rows [w*16, w*16+16) and ALL 64 keys of the tile ->
// warp tile 16x64 for S and 16x64 for O; softmax rows never cross warps
// (row reductions = 2 shfl_xor; P consumed by the same warp, __syncwarp only).
//
// Smem layouts (tf32 words; strides = 8 mod 32 -> conflict-free frags):
//   Qs[d][q]   stride 136 (transposed once at load; A-frags k-major)
//   Ks[key][d] stride 72  (natural; B-frag addressing does the transpose)
//   Vs[key][d] stride 72  (natural)
//   Ps[q][key] stride 72  (P staged per tile, m-major, written as uint2)
//   Gs[64] float
// ---------------------------------------------------------------------------
#define FBQ   128
#define FBK   64
#define FQSTR 136
#define FKSTR 72
#define FPSTR 72

#define FQS_OFF 0                                   // Qs: 64*136 = 8704
#define FKS_OFF (FQS_OFF + D_HEAD * FQSTR)          // Ks: 64*72  = 4608
#define FVS_OFF (FKS_OFF + FBK * FKSTR)             // Vs: 64*72  = 4608
#define FPS_OFF (FVS_OFF + FBK * FKSTR)             // Ps: 128*72 = 9216
#define FGS_OFF (FPS_OFF + FBQ * FPSTR)             // Gs: 64
#define FSMEM_WORDS (FGS_OFF + FBK)                 // 27200
#define FSMEM_BYTES (FSMEM_WORDS * 4)               // 108800

__global__ __launch_bounds__(256, 2) void flash_attn3_kernel(
    const int* __restrict__ mask, const float* __restrict__ gauss)
{
    extern __shared__ unsigned fsm[];
    unsigned* const Qs = fsm + FQS_OFF;
    unsigned* const Ks = fsm + FKS_OFF;
    unsigned* const Vs = fsm + FVS_OFF;
    unsigned* const Ps = fsm + FPS_OFF;
    float*    const Gs = (float*)(fsm + FGS_OFF);

    const int tid  = threadIdx.x;
    const int lane = tid & 31;
    const int wid  = tid >> 5;        // 0..7
    const int gid  = lane >> 2;       // 0..7
    const int tg   = lane & 3;        // 0..3
    const int mb   = wid * 16;        // warp's query-row base

    const int b     = blockIdx.z;
    const int h     = blockIdx.y;
    const int qbase = blockIdx.x * FBQ;

    // ---- load Q block transposed into Qs[d][q] as tf32 (once) ----
    {
        const float* qg = g_q + ((size_t)(b * SEQ + qbase)) * DIM + h * D_HEAD;
        #pragma unroll
        for (int c = 0; c < 8; c++) {
            int flat = (c * 256 + tid) * 4;       // 8192 floats
            int qr = flat >> 6;                    // 0..127
            int d  = flat & 63;
            float4 v = *(const float4*)(qg + (size_t)qr * DIM + d);
            Qs[(d + 0) * FQSTR + qr] = f2tf32(v.x);
            Qs[(d + 1) * FQSTR + qr] = f2tf32(v.y);
            Qs[(d + 2) * FQSTR + qr] = f2tf32(v.z);
            Qs[(d + 3) * FQSTR + qr] = f2tf32(v.w);
        }
    }

    float m_run[2], l_run[2];
    float acc_o[8][4];
    m_run[0] = m_run[1] = -1e30f;
    l_run[0] = l_run[1] = 0.f;
    #pragma unroll
    for (int u = 0; u < 8; u++)
        #pragma unroll
        for (int r = 0; r < 4; r++) acc_o[u][r] = 0.f;

    for (int kt = 0; kt < SEQ; kt += FBK) {
        __syncthreads();   // Q ready (1st iter) / all warps done with prev K,V

        // ---- load K, V natural (tf32), Gs ----
        {
            const float* kg = g_k + ((size_t)(b * SEQ + kt)) * DIM + h * D_HEAD;
            const float* vg = g_v + ((size_t)(b * SEQ + kt)) * DIM + h * D_HEAD;
            #pragma unroll
            for (int c = 0; c < 4; c++) {
                int flat = (c * 256 + tid) * 4;    // 4096 floats each
                int kr = flat >> 6;                 // 0..63
                int d  = flat & 63;
                float4 kv = *(const float4*)(kg + (size_t)kr * DIM + d);
                float4 vv = *(const float4*)(vg + (size_t)kr * DIM + d);
                uint4 ku, vu;
                ku.x = f2tf32(kv.x); ku.y = f2tf32(kv.y);
                ku.z = f2tf32(kv.z); ku.w = f2tf32(kv.w);
                vu.x = f2tf32(vv.x); vu.y = f2tf32(vv.y);
                vu.z = f2tf32(vv.z); vu.w = f2tf32(vv.w);
                *(uint4*)(Ks + kr * FKSTR + d) = ku;
                *(uint4*)(Vs + kr * FKSTR + d) = vu;
            }
            if (tid < FBK) {
                int kk = kt + tid;
                float g = gauss[b * SEQ + kk] + 1e-10f;
                Gs[tid] = (mask[b * SEQ + kk] == 0) ? 0.f : g;
            }
        }
        __syncthreads();   // tile visible

        // ---- S = Q · K^T : warp tile 16(q) x 64(k), K-dim = 64 ----
        float acc_s[8][4];
        #pragma unroll
        for (int u = 0; u < 8; u++)
            #pragma unroll
            for (int r = 0; r < 4; r++) acc_s[u][r] = 0.f;

        #pragma unroll
        for (int kb = 0; kb < D_HEAD; kb += 8) {
            unsigned af0, af1, af2, af3, bf0[8], bf1[8];
            af0 = Qs[(kb + tg    ) * FQSTR + mb + gid];
            af1 = Qs[(kb + tg    ) * FQSTR + mb + gid + 8];
            af2 = Qs[(kb + tg + 4) * FQSTR + mb + gid];
            af3 = Qs[(kb + tg + 4) * FQSTR + mb + gid + 8];
            #pragma unroll
            for (int u = 0; u < 8; u++) {
                const int n0 = u * 8 + gid;        // key index
                bf0[u] = Ks[n0 * FKSTR + kb + tg    ];   // B[k][n] = K[n][k]
                bf1[u] = Ks[n0 * FKSTR + kb + tg + 4];
            }
            #pragma unroll
            for (int u = 0; u < 8; u++)
                mma_tf32(acc_s[u], af0, af1, af2, af3, bf0[u], bf1[u]);
        }

        // ---- online softmax (FMA-pipe exp), gauss/mask folded ----
        float g2v[8][2];
        #pragma unroll
        for (int u = 0; u < 8; u++) {
            float2 gg = *(const float2*)(Gs + u * 8 + tg * 2);
            g2v[u][0] = gg.x; g2v[u][1] = gg.y;
        }

        float osc[2];
        #pragma unroll
        for (int rh = 0; rh < 2; rh++) {
            float lm = -1e30f;
            #pragma unroll
            for (int u = 0; u < 8; u++) {
                float e0 = (g2v[u][0] > 0.f) ? acc_s[u][rh*2+0] : -1e30f;
                float e1 = (g2v[u][1] > 0.f) ? acc_s[u][rh*2+1] : -1e30f;
                lm = fmaxf(lm, fmaxf(e0, e1));
            }
            lm = fmaxf(lm, __shfl_xor_sync(0xffffffffu, lm, 1));
            lm = fmaxf(lm, __shfl_xor_sync(0xffffffffu, lm, 2));

            const float mnew = fmaxf(m_run[rh], lm);
            const float scl  = fast_exp2((m_run[rh] - mnew) * LOG2E);
            const float mlg  = mnew * LOG2E;
            float rs = 0.f;
            #pragma unroll
            for (int u = 0; u < 8; u++) {
                #pragma unroll
                for (int c = 0; c < 2; c++) {
                    float x = fmaf(acc_s[u][rh*2+c], LOG2E, -mlg);
                    float p = fast_exp2(x) * g2v[u][c];   // masked: g=0 -> p=0
                    acc_s[u][rh*2+c] = p;
                    rs += p;
                }
            }
            rs += __shfl_xor_sync(0xffffffffu, rs, 1);
            rs += __shfl_xor_sync(0xffffffffu, rs, 2);

            l_run[rh] = l_run[rh] * scl + rs;
            m_run[rh] = mnew;
            osc[rh]   = scl;
        }
        #pragma unroll
        for (int u = 0; u < 8; u++)
            #pragma unroll
            for (int r = 0; r < 4; r++) acc_o[u][r] *= osc[r >> 1];

        // ---- stage P (tf32) to Ps[q][key]; same warp consumes it ----
        #pragma unroll
        for (int rh = 0; rh < 2; rh++) {
            const int qrow = mb + gid + rh * 8;
            #pragma unroll
            for (int u = 0; u < 8; u++) {
                uint2 pv;
                pv.x = f2tf32(acc_s[u][rh*2+0]);
                pv.y = f2tf32(acc_s[u][rh*2+1]);
                *(uint2*)(Ps + qrow * FPSTR + u * 8 + tg * 2) = pv;
            }
        }
        __syncwarp();

        // ---- O += P · V : warp tile 16(q) x 64(d), K-dim = 64 keys ----
        #pragma unroll
        for (int kb = 0; kb < FBK; kb += 8) {
            unsigned af0, af1, af2, af3, bf0[8], bf1[8];
            af0 = Ps[(mb + gid    ) * FPSTR + kb + tg    ];
            af1 = Ps[(mb + gid + 8) * FPSTR + kb + tg    ];
            af2 = Ps[(mb + gid    ) * FPSTR + kb + tg + 4];
            af3 = Ps[(mb + gid + 8) * FPSTR + kb + tg + 4];
            #pragma unroll
            for (int u = 0; u < 8; u++) {
                const int n0 = u * 8 + gid;        // head-dim index
                bf0[u] = Vs[(kb + tg    ) * FKSTR + n0];
                bf1[u] = Vs[(kb + tg + 4) * FKSTR + n0];
            }
            #pragma unroll
            for (int u = 0; u < 8; u++)
                mma_tf32(acc_o[u], af0, af1, af2, af3, bf0[u], bf1[u]);
        }
    }

    // ---- epilogue: normalize and store ----
    #pragma unroll
    for (int rh = 0; rh < 2; rh++) {
        const float inv = 1.f / l_run[rh];
        const int qrow = qbase + mb + gid + rh * 8;
        float* op = g_ctx + ((size_t)(b * SEQ + qrow)) * DIM + h * D_HEAD;
        #pragma unroll
        for (int u = 0; u < 8; u++) {
            float2 ov;
            ov.x = acc_o[u][rh*2+0] * inv;
            ov.y = acc_o[u][rh*2+1] * inv;
            *(float2*)(op + u * 8 + tg * 2) = ov;
        }
    }
}

// ---------------------------------------------------------------------------
// Launch
// inputs: 0=query 1=key 2=value 3=mask 4=gauss_weight
//         5=Wq 6=bq 7=Wk 8=bk 9=Wv 10=bv 11=Wo 12=bo
// ---------------------------------------------------------------------------
extern "C" void kernel_launch(void* const* d_in, const int* in_sizes, int n_in,
                              void* d_out, int out_size)
{
    const float* query = (const float*)d_in[0];
    const float* key   = (const float*)d_in[1];
    const float* value = (const float*)d_in[2];
    const int*   mask  = (const int*)  d_in[3];
    const float* gauss = (const float*)d_in[4];
    const float* Wq = (const float*)d_in[5];
    const float* bq = (const float*)d_in[6];
    const float* Wk = (const float*)d_in[7];
    const float* bk = (const float*)d_in[8];
    const float* Wv = (const float*)d_in[9];
    const float* bv = (const float*)d_in[10];
    const float* Wo = (const float*)d_in[11];
    const float* bo = (const float*)d_in[12];
    float* out = (float*)d_out;

    float *pq, *pk, *pv, *pctx;
    cudaGetSymbolAddress((void**)&pq,   g_q);
    cudaGetSymbolAddress((void**)&pk,   g_k);
    cudaGetSymbolAddress((void**)&pv,   g_v);
    cudaGetSymbolAddress((void**)&pctx, g_ctx);

    // allow >48KB dynamic smem (idempotent host calls, not stream ops ->
    // safe under graph capture)
    cudaFuncSetAttribute(tf32_gemm_kernel,
                         cudaFuncAttributeMaxDynamicSharedMemorySize,
                         GEMM_SMEM_BYTES);
    cudaFuncSetAttribute(flash_attn3_kernel,
                         cudaFuncAttributeMaxDynamicSharedMemorySize,
                         FSMEM_BYTES);

    dim3 ggrid(DIM / GBN, MROWS / GBM);   // (8, 16) = 128 blocks
    const float qscale = 1.0f / 8.0f;     // 1/sqrt(D_HEAD)

    tf32_gemm_kernel<<<ggrid, 512, GEMM_SMEM_BYTES>>>(query, Wq, bq, pq, qscale);
    tf32_gemm_kernel<<<ggrid, 512, GEMM_SMEM_BYTES>>>(key,   Wk, bk, pk, 1.0f);
    tf32_gemm_kernel<<<ggrid, 512, GEMM_SMEM_BYTES>>>(value, Wv, bv, pv, 1.0f);

    dim3 agrid(SEQ / FBQ, N_HEADS, BS);   // (8, 16, 4)
    flash_attn3_kernel<<<agrid, 256, FSMEM_BYTES>>>(mask, gauss);

    tf32_gemm_kernel<<<ggrid, 512, GEMM_SMEM_BYTES>>>(pctx, Wo, bo, out, 1.0f);
}